// round 13
// baseline (speedup 1.0000x reference)
#include <cuda_runtime.h>
#include <cuda_fp16.h>
#include <math.h>
#include <cstdint>

#define B_   2
#define S_   2048
#define H_   2048
#define NH_  32
#define NKV_ 8
#define DH_  64
#define M_   (B_*S_)      // 4096 rows
#define KA_  4096         // A' k-ext: [hi | lo]
#define KW_  2048         // W stored once (hi); k-index wraps

typedef unsigned long long u64;

// ---------------------------------------------------------------------------
// Scratch (static device globals; no runtime allocation)
// ---------------------------------------------------------------------------
__device__ float g_q[(size_t)M_ * NH_ * DH_];     // fp32 QKV intermediates
__device__ float g_k[(size_t)M_ * NKV_ * DH_];
__device__ float g_v[(size_t)M_ * NKV_ * DH_];
__device__ float g_invfreq[DH_ / 2];

__device__ __align__(128) __half g_a2 [(size_t)M_   * KA_];  // X'=[hi|lo], then O'
__device__ __align__(128) __half g_wq2[(size_t)2048 * KW_];  // [N,2048] hi only
__device__ __align__(128) __half g_wk2[(size_t)512  * KW_];
__device__ __align__(128) __half g_wv2[(size_t)512  * KW_];
__device__ __align__(128) __half g_wo2[(size_t)2048 * KW_];

// split attention operands
__device__ __align__(128) __half g_q2 [(size_t)B_ * NH_  * S_ * 128]; // [qh64|ql64], pre-scaled 1/8
__device__ __align__(128) __half g_k2 [(size_t)B_ * NKV_ * S_ * 64];  // kh only
__device__ __align__(128) __half g_v2t[(size_t)B_ * NKV_ * 64 * S_];  // [d][s] vh only

// ---------------------------------------------------------------------------
// helpers
// ---------------------------------------------------------------------------
__device__ __forceinline__ void mma16816(float* d, const uint32_t* a, const uint32_t* b) {
    asm volatile("mma.sync.aligned.m16n8k16.row.col.f32.f16.f16.f32 "
                 "{%0,%1,%2,%3}, {%4,%5,%6,%7}, {%8,%9}, {%0,%1,%2,%3};"
                 : "+f"(d[0]), "+f"(d[1]), "+f"(d[2]), "+f"(d[3])
                 : "r"(a[0]), "r"(a[1]), "r"(a[2]), "r"(a[3]), "r"(b[0]), "r"(b[1]));
}
__device__ __forceinline__ uint32_t packh(float a, float b) {
    __half2 p = __halves2half2(__float2half_rn(a), __float2half_rn(b));
    return *(uint32_t*)&p;
}
__device__ __forceinline__ uint32_t smem_u32(const void* p) {
    uint32_t a;
    asm("{ .reg .u64 t; cvta.to.shared.u64 t, %1; cvt.u32.u64 %0, t; }" : "=r"(a) : "l"(p));
    return a;
}
__device__ __forceinline__ void ldmx4(uint32_t& r0, uint32_t& r1, uint32_t& r2, uint32_t& r3,
                                      uint32_t a) {
    asm volatile("ldmatrix.sync.aligned.m8n8.x4.shared.b16 {%0,%1,%2,%3}, [%4];"
                 : "=r"(r0), "=r"(r1), "=r"(r2), "=r"(r3) : "r"(a));
}
__device__ __forceinline__ void cpa16(uint32_t s, const void* g) {
    asm volatile("cp.async.ca.shared.global [%0], [%1], 16;" :: "r"(s), "l"(g));
}
#define CP_COMMIT() asm volatile("cp.async.commit_group;" ::: "memory")
#define CP_WAIT2()  asm volatile("cp.async.wait_group 2;" ::: "memory")
#define CP_WAIT0()  asm volatile("cp.async.wait_group 0;" ::: "memory")

// ---------------------------------------------------------------------------
// inv_freq init
// ---------------------------------------------------------------------------
__global__ void invfreq_init_kernel() {
    int i = threadIdx.x;
    if (i < DH_ / 2) {
        g_invfreq[i] = (float)(1.0 / pow(10000.0, (double)(2 * i) / (double)DH_));
    }
}

// ---------------------------------------------------------------------------
// hi/lo split: src fp32 [4096, 2048] -> dst f16 [4096, 4096] = [hi|lo]
// ---------------------------------------------------------------------------
__global__ __launch_bounds__(256) void cvt_hilo(const float* __restrict__ src,
                                                __half* __restrict__ dst)
{
    int t = blockIdx.x * blockDim.x + threadIdx.x;
    int m  = t >> 9;
    int c4 = (t & 511) * 4;
    float4 x = *(const float4*)(src + (size_t)m * 2048 + c4);

    __half h0 = __float2half_rn(x.x), h1 = __float2half_rn(x.y);
    __half h2 = __float2half_rn(x.z), h3 = __float2half_rn(x.w);
    __half l0 = __float2half_rn(x.x - __half2float(h0));
    __half l1 = __float2half_rn(x.y - __half2float(h1));
    __half l2 = __float2half_rn(x.z - __half2float(h2));
    __half l3 = __float2half_rn(x.w - __half2float(h3));

    __half2 H01 = __halves2half2(h0, h1), H23 = __halves2half2(h2, h3);
    __half2 L01 = __halves2half2(l0, l1), L23 = __halves2half2(l2, l3);
    uint2 Hv = make_uint2(*(uint32_t*)&H01, *(uint32_t*)&H23);
    uint2 Lv = make_uint2(*(uint32_t*)&L01, *(uint32_t*)&L23);

    size_t base = (size_t)m * KA_ + c4;
    *(uint2*)(dst + base)        = Hv;
    *(uint2*)(dst + base + 2048) = Lv;
}

// ---------------------------------------------------------------------------
// Fused weight transpose: all four W at once.
// blockIdx.x: 0..63 Wq | 64..79 Wk | 80..95 Wv | 96..159 Wo
// ---------------------------------------------------------------------------
__global__ __launch_bounds__(256) void cvt_w_all(const float* __restrict__ Wq,
                                                 const float* __restrict__ Wk,
                                                 const float* __restrict__ Wv,
                                                 const float* __restrict__ Wo,
                                                 __half* __restrict__ Pq,
                                                 __half* __restrict__ Pk,
                                                 __half* __restrict__ Pv,
                                                 __half* __restrict__ Po)
{
    __shared__ float tile[32][33];
    int tx = threadIdx.x, ty = threadIdx.y;
    int bxx = blockIdx.x;

    const float* W; __half* Wp; int Nout, nb;
    if (bxx < 64)       { W = Wq; Wp = Pq; Nout = 2048; nb = bxx; }
    else if (bxx < 80)  { W = Wk; Wp = Pk; Nout = 512;  nb = bxx - 64; }
    else if (bxx < 96)  { W = Wv; Wp = Pv; Nout = 512;  nb = bxx - 80; }
    else                { W = Wo; Wp = Po; Nout = 2048; nb = bxx - 96; }

    int n0 = nb * 32, k0 = blockIdx.y * 32;

    #pragma unroll
    for (int r = 0; r < 4; r++)
        tile[ty + r * 8][tx] = W[(size_t)(k0 + ty + r * 8) * Nout + n0 + tx];
    __syncthreads();

    #pragma unroll
    for (int r = 0; r < 4; r++) {
        int nl = ty + r * 8, kl = tx;
        Wp[(size_t)(n0 + nl) * KW_ + k0 + kl] = __float2half_rn(tile[kl][nl]);
    }
}

// ---------------------------------------------------------------------------
// f16 mma.sync GEMM: C = A'[M,4096] @ W'[N,2048,wrapped]^T
// 128x128 CTA tile, 8 warps (2x4), K-slab 32.
// cp.async 4-stage pipeline (wait_group 2), ldmatrix fragment loads.
// ---------------------------------------------------------------------------
#define KSLAB 32
#define NSLAB (KA_ / KSLAB)     // 128
#define ARS   40                // smem row stride in halves (80 B)
#define BUFH  (128 * ARS)       // halves per buffer
#define NSTG  4
#define GSM_BYTES (2 * NSTG * BUFH * 2)   // 4 A bufs + 4 B bufs = 81920 B

__device__ __forceinline__ void mma_gemm_body(
    const __half* __restrict__ A2, const __half* __restrict__ W2,
    float* __restrict__ C, int Nout, int row0, int col0)
{
    extern __shared__ __half gsm[];
    __half* Asp = gsm;                   // NSTG x BUFH
    __half* Bsp = gsm + NSTG * BUFH;     // NSTG x BUFH

    const int tid  = threadIdx.x;
    const int lane = tid & 31;
    const int wid  = tid >> 5;
    const int wm   = wid >> 2;
    const int wn   = wid & 3;
    const int g    = lane >> 2;
    const int tq   = lane & 3;

    const int lrow = tid >> 2;
    const int lk   = (tid & 3) * 8;

    const __half* Ag = A2 + (size_t)(row0 + lrow) * KA_ + lk;
    const __half* Bg = W2 + (size_t)(col0 + lrow) * KW_ + lk;

    const uint32_t AROW = ARS * 2;
    uint32_t aB[NSTG], bB[NSTG], aD[NSTG], bD[NSTG];
    #pragma unroll
    for (int u = 0; u < NSTG; u++) {
        aB[u] = smem_u32(Asp + u * BUFH + (wm * 64 + (lane & 15)) * ARS + (lane >> 4) * 8);
        bB[u] = smem_u32(Bsp + u * BUFH + (wn * 32 + (lane >> 4) * 8 + (lane & 7)) * ARS
                         + ((lane >> 3) & 1) * 8);
        aD[u] = smem_u32(Asp + u * BUFH + lrow * ARS + lk);
        bD[u] = smem_u32(Bsp + u * BUFH + lrow * ARS + lk);
    }

    float acc[4][4][4];
    #pragma unroll
    for (int i = 0; i < 4; i++)
        #pragma unroll
        for (int j = 0; j < 4; j++)
            #pragma unroll
            for (int c = 0; c < 4; c++) acc[i][j][c] = 0.f;

    auto issue_slab = [&](int s, int u) {
        const int ka = s * KSLAB;
        const int kw = ka & (KW_ - 1);
        cpa16(aD[u],                 Ag + ka);
        cpa16(aD[u] + 64 * AROW,     Ag + ka + (size_t)64 * KA_);
        cpa16(bD[u],                 Bg + kw);
        cpa16(bD[u] + 64 * AROW,     Bg + kw + (size_t)64 * KW_);
    };

    issue_slab(0, 0); CP_COMMIT();
    issue_slab(1, 1); CP_COMMIT();
    issue_slab(2, 2); CP_COMMIT();

    int buf = 0;
    for (int s = 0; s < NSLAB; s++) {
        CP_WAIT2();           // slab s resident (s+1, s+2 may be pending)
        __syncthreads();

        #pragma unroll
        for (int ks = 0; ks < 2; ks++) {
            uint32_t af[4][4];
            #pragma unroll
            for (int mt = 0; mt < 4; mt++)
                ldmx4(af[mt][0], af[mt][1], af[mt][2], af[mt][3],
                      aB[buf] + (uint32_t)(mt * 16) * AROW + ks * 32);
            uint32_t bf[4][2];
            ldmx4(bf[0][0], bf[0][1], bf[1][0], bf[1][1], bB[buf] + ks * 32);
            ldmx4(bf[2][0], bf[2][1], bf[3][0], bf[3][1],
                  bB[buf] + (uint32_t)16 * AROW + ks * 32);

            #pragma unroll
            for (int mt = 0; mt < 4; mt++)
                #pragma unroll
                for (int nt = 0; nt < 4; nt++)
                    mma16816(acc[mt][nt], af[mt], bf[nt]);
        }

        // slab s+3 reuses buffer (s+3)%4 == (s-1)%4, last read one sync ago
        if (s + 3 < NSLAB) issue_slab(s + 3, (s + 3) % NSTG);
        CP_COMMIT();          // commit every iteration (possibly empty group)
        buf = (buf + 1) % NSTG;
    }

    #pragma unroll
    for (int mt = 0; mt < 4; mt++) {
        #pragma unroll
        for (int nt = 0; nt < 4; nt++) {
            int row = row0 + wm * 64 + mt * 16 + g;
            int col = col0 + wn * 32 + nt * 8 + tq * 2;
            *(float2*)&C[(size_t)row * Nout + col] =
                make_float2(acc[mt][nt][0], acc[mt][nt][1]);
            *(float2*)&C[(size_t)(row + 8) * Nout + col] =
                make_float2(acc[mt][nt][2], acc[mt][nt][3]);
        }
    }
}

__global__ __launch_bounds__(256, 2) void qkv_mma()
{
    const int bx = blockIdx.x;
    if (bx < 512)
        mma_gemm_body(g_a2, g_wq2, g_q, NH_ * DH_, (bx >> 4) * 128, (bx & 15) * 128);
    else if (bx < 640) {
        int t = bx - 512;
        mma_gemm_body(g_a2, g_wk2, g_k, NKV_ * DH_, (t >> 2) * 128, (t & 3) * 128);
    } else {
        int t = bx - 640;
        mma_gemm_body(g_a2, g_wv2, g_v, NKV_ * DH_, (t >> 2) * 128, (t & 3) * 128);
    }
}

__global__ __launch_bounds__(256, 2) void out_mma(float* __restrict__ out)
{
    const int bx = blockIdx.x;
    mma_gemm_body(g_a2, g_wo2, out, H_, (bx >> 4) * 128, (bx & 15) * 128);
}

// ---------------------------------------------------------------------------
// RoPE + split: g_q -> g_q2 [qh|ql] scaled 1/8 ; g_k -> g_k2 [kh] only
// ---------------------------------------------------------------------------
__global__ __launch_bounds__(256) void rope_split_kernel(const int* __restrict__ pos_ids)
{
    const int TOT = M_ * (NH_ + NKV_) * 32;
    int t = blockIdx.x * blockDim.x + threadIdx.x;
    if (t >= TOT) return;

    int i  = t & 31;
    int h  = (t >> 5) % (NH_ + NKV_);
    int bs = t / (32 * (NH_ + NKV_));
    int b  = bs >> 11, s = bs & 2047;

    float pos = (float)pos_ids[bs];
    float f = pos * g_invfreq[i];
    float sn, c;
    sincosf(f, &sn, &c);

    if (h < NH_) {
        const float* base = g_q + (size_t)bs * (NH_ * DH_) + h * DH_;
        __half* dst = g_q2 + ((size_t)(b * NH_ + h) * S_ + s) * 128;
        float x1 = base[i], x2 = base[i + 32];
        float o1 = (x1 * c - x2 * sn) * 0.125f;
        float o2 = (x2 * c + x1 * sn) * 0.125f;
        __half h1 = __float2half_rn(o1);
        __half h2 = __float2half_rn(o2);
        dst[i]           = h1;
        dst[i + 32]      = h2;
        dst[64 + i]      = __float2half_rn(o1 - __half2float(h1));
        dst[64 + i + 32] = __float2half_rn(o2 - __half2float(h2));
    } else {
        const float* base = g_k + (size_t)bs * (NKV_ * DH_) + (h - NH_) * DH_;
        __half* dst = g_k2 + ((size_t)(b * NKV_ + (h - NH_)) * S_ + s) * 64;
        float x1 = base[i], x2 = base[i + 32];
        dst[i]      = __float2half_rn(x1 * c - x2 * sn);
        dst[i + 32] = __float2half_rn(x2 * c + x1 * sn);
    }
}

// ---------------------------------------------------------------------------
// V transpose: g_v fp32 [m][512] -> g_v2t f16 [b][kvh][d][s] (hi only)
// ---------------------------------------------------------------------------
__global__ __launch_bounds__(256) void cvt_v_kernel()
{
    __shared__ float tile[32][33];
    int tx = threadIdx.x, ty = threadIdx.y;
    int s0 = blockIdx.x * 32;
    int cb = blockIdx.y;
    int b  = blockIdx.z;
    int kvh = cb >> 1, dbase = (cb & 1) * 32;

    #pragma unroll
    for (int r = 0; r < 4; r++)
        tile[ty + r * 8][tx] = g_v[(size_t)(b * S_ + s0 + ty + r * 8) * 512 + cb * 32 + tx];
    __syncthreads();

    #pragma unroll
    for (int r = 0; r < 4; r++) {
        int dl = ty + r * 8;
        size_t obase = ((size_t)(b * NKV_ + kvh) * 64 + dbase + dl) * S_;
        g_v2t[obase + s0 + tx] = __float2half_rn(tile[tx][dl]);
    }
}

// ---------------------------------------------------------------------------
// Flash attention on HMMA, f16 2-term splits (unchanged from R12).
// ---------------------------------------------------------------------------
#define KSP   72                        // K/Vt smem stride (f16)

__global__ __launch_bounds__(256) void flash_mma()
{
    __shared__ __half Ks[2][64 * KSP];
    __shared__ __half Vt[2][64 * KSP];

    const int tid  = threadIdx.x;
    const int lane = tid & 31;
    const int wq   = tid >> 5;
    const int g    = lane >> 2;
    const int tq   = lane & 3;

    const int jq  = (gridDim.x - 1) - blockIdx.x;
    const int h   = blockIdx.y;
    const int b   = blockIdx.z;
    const int kvh = h >> 2;
    const int q0  = jq * 128;

    const __half* qbase = g_q2 + ((size_t)(b * NH_ + h) * S_ + q0 + wq * 16) * 128;
    const __half* kbase = g_k2 + (size_t)(b * NKV_ + kvh) * S_ * 64;
    const __half* vbase = g_v2t + (size_t)(b * NKV_ + kvh) * 64 * S_;

    const int lr  = tid >> 2;       // 0..63
    const int lsg = tid & 3;        // 16-half segment

    const uint32_t KROW = KSP * 2;
    uint32_t kB[2], vB[2], kD[2], vD[2];
    #pragma unroll
    for (int u = 0; u < 2; u++) {
        kB[u] = smem_u32(&Ks[u][((lane >> 4) * 8 + (lane & 7)) * KSP + ((lane >> 3) & 1) * 8]);
        vB[u] = smem_u32(&Vt[u][((lane >> 4) * 8 + (lane & 7)) * KSP + ((lane >> 3) & 1) * 8]);
        kD[u] = smem_u32(&Ks[u][lr * KSP + lsg * 16]);
        vD[u] = smem_u32(&Vt[u][lr * KSP + lsg * 16]);
    }

    auto issue_kv = [&](int jt, int u) {
        const __half* ks = kbase + (size_t)(jt * 64 + lr) * 64 + lsg * 16;
        const __half* vs = vbase + (size_t)lr * S_ + jt * 64 + lsg * 16;
        cpa16(kD[u],      ks);
        cpa16(kD[u] + 16, ks + 8);
        cpa16(vD[u],      vs);
        cpa16(vD[u] + 16, vs + 8);
    };

    uint32_t qf[8][4];
    #pragma unroll
    for (int pc = 0; pc < 8; pc++) {
        int c = pc * 16 + tq * 2;
        qf[pc][0] = *(const uint32_t*)(qbase + (size_t)g * 128 + c);
        qf[pc][1] = *(const uint32_t*)(qbase + (size_t)(g + 8) * 128 + c);
        qf[pc][2] = *(const uint32_t*)(qbase + (size_t)g * 128 + c + 8);
        qf[pc][3] = *(const uint32_t*)(qbase + (size_t)(g + 8) * 128 + c + 8);
    }

    float m0 = -1e30f, m1 = -1e30f, l0 = 0.f, l1 = 0.f;
    float accO[8][4];
    #pragma unroll
    for (int nt = 0; nt < 8; nt++)
        #pragma unroll
        for (int c = 0; c < 4; c++) accO[nt][c] = 0.f;

    issue_kv(0, 0); CP_COMMIT();
    CP_WAIT0();
    __syncthreads();

    int fb = 0;
    const int ntiles = 2 * jq + 2;
    for (int jt = 0; jt < ntiles; jt++) {
        const bool more = (jt + 1 < ntiles);
        if (more) { issue_kv(jt + 1, fb ^ 1); CP_COMMIT(); }

        float sa[8][4];
        #pragma unroll
        for (int nt = 0; nt < 8; nt++)
            #pragma unroll
            for (int c = 0; c < 4; c++) sa[nt][c] = 0.f;

        #pragma unroll
        for (int kc = 0; kc < 4; kc++) {
            uint32_t bf[8][2];
            #pragma unroll
            for (int ntp = 0; ntp < 4; ntp++)
                ldmx4(bf[2*ntp][0], bf[2*ntp][1], bf[2*ntp+1][0], bf[2*ntp+1][1],
                      kB[fb] + (uint32_t)(ntp * 16) * KROW + kc * 32);
            #pragma unroll
            for (int nt = 0; nt < 8; nt++) {
                mma16816(sa[nt], qf[kc],     bf[nt]);
                mma16816(sa[nt], qf[kc + 4], bf[nt]);
            }
        }

        const float NEG = -1e30f;
        if (jt >= 2 * jq) {
            int rg0 = q0 + wq * 16 + g, rg1 = rg0 + 8;
            #pragma unroll
            for (int nt = 0; nt < 8; nt++) {
                int cg = jt * 64 + nt * 8 + tq * 2;
                if (cg     > rg0) sa[nt][0] = NEG;
                if (cg + 1 > rg0) sa[nt][1] = NEG;
                if (cg     > rg1) sa[nt][2] = NEG;
                if (cg + 1 > rg1) sa[nt][3] = NEG;
            }
        }

        float rm0 = NEG, rm1 = NEG;
        #pragma unroll
        for (int nt = 0; nt < 8; nt++) {
            rm0 = fmaxf(rm0, fmaxf(sa[nt][0], sa[nt][1]));
            rm1 = fmaxf(rm1, fmaxf(sa[nt][2], sa[nt][3]));
        }
        rm0 = fmaxf(rm0, __shfl_xor_sync(0xffffffffu, rm0, 1));
        rm0 = fmaxf(rm0, __shfl_xor_sync(0xffffffffu, rm0, 2));
        rm1 = fmaxf(rm1, __shfl_xor_sync(0xffffffffu, rm1, 1));
        rm1 = fmaxf(rm1, __shfl_xor_sync(0xffffffffu, rm1, 2));

        float mn0 = fmaxf(m0, rm0), mn1 = fmaxf(m1, rm1);
        float al0 = __expf(m0 - mn0), al1 = __expf(m1 - mn1);
        m0 = mn0; m1 = mn1;

        float rs0 = 0.f, rs1 = 0.f;
        float p[8][4];
        #pragma unroll
        for (int nt = 0; nt < 8; nt++) {
            p[nt][0] = __expf(sa[nt][0] - mn0);
            p[nt][1] = __expf(sa[nt][1] - mn0);
            p[nt][2] = __expf(sa[nt][2] - mn1);
            p[nt][3] = __expf(sa[nt][3] - mn1);
            rs0 += p[nt][0] + p[nt][1];
            rs1 += p[nt][2] + p[nt][3];
        }
        rs0 += __shfl_xor_sync(0xffffffffu, rs0, 1);
        rs0 += __shfl_xor_sync(0xffffffffu, rs0, 2);
        rs1 += __shfl_xor_sync(0xffffffffu, rs1, 1);
        rs1 += __shfl_xor_sync(0xffffffffu, rs1, 2);
        l0 = l0 * al0 + rs0;
        l1 = l1 * al1 + rs1;

        #pragma unroll
        for (int nt = 0; nt < 8; nt++) {
            accO[nt][0] *= al0; accO[nt][1] *= al0;
            accO[nt][2] *= al1; accO[nt][3] *= al1;
        }

        #pragma unroll
        for (int vc = 0; vc < 4; vc++) {
            float p00 = p[2*vc][0],   p01 = p[2*vc][1];
            float p02 = p[2*vc][2],   p03 = p[2*vc][3];
            float p10 = p[2*vc+1][0], p11 = p[2*vc+1][1];
            float p12 = p[2*vc+1][2], p13 = p[2*vc+1][3];
            uint32_t aph[4], apl[4];
            aph[0] = packh(p00, p01);
            aph[1] = packh(p02, p03);
            aph[2] = packh(p10, p11);
            aph[3] = packh(p12, p13);
            apl[0] = packh(p00 - __half2float(__float2half_rn(p00)),
                           p01 - __half2float(__float2half_rn(p01)));
            apl[1] = packh(p02 - __half2float(__float2half_rn(p02)),
                           p03 - __half2float(__float2half_rn(p03)));
            apl[2] = packh(p10 - __half2float(__float2half_rn(p10)),
                           p11 - __half2float(__float2half_rn(p11)));
            apl[3] = packh(p12 - __half2float(__float2half_rn(p12)),
                           p13 - __half2float(__float2half_rn(p13)));

            uint32_t bf[8][2];
            #pragma unroll
            for (int ntp = 0; ntp < 4; ntp++)
                ldmx4(bf[2*ntp][0], bf[2*ntp][1], bf[2*ntp+1][0], bf[2*ntp+1][1],
                      vB[fb] + (uint32_t)(ntp * 16) * KROW + vc * 32);
            #pragma unroll
            for (int nt = 0; nt < 8; nt++) {
                mma16816(accO[nt], aph, bf[nt]);
                mma16816(accO[nt], apl, bf[nt]);
            }
        }

        if (more) {
            CP_WAIT0();
            __syncthreads();
            fb ^= 1;
        }
    }

    float inv0 = 1.f / l0, inv1 = 1.f / l1;
    size_t r0 = (size_t)b * S_ + q0 + wq * 16 + g;
    #pragma unroll
    for (int nt = 0; nt < 8; nt++) {
        int c = h * 64 + nt * 8 + tq * 2;
        float o00 = accO[nt][0] * inv0, o01 = accO[nt][1] * inv0;
        float o10 = accO[nt][2] * inv1, o11 = accO[nt][3] * inv1;

        __half h00 = __float2half_rn(o00), h01 = __float2half_rn(o01);
        __half h10 = __float2half_rn(o10), h11 = __float2half_rn(o11);

        __half* d0 = g_a2 + r0 * KA_ + c;
        __half* d1 = g_a2 + (r0 + 8) * KA_ + c;
        *(uint32_t*)(d0)        = packh(o00, o01);
        *(uint32_t*)(d0 + 2048) = packh(o00 - __half2float(h00), o01 - __half2float(h01));
        *(uint32_t*)(d1)        = packh(o10, o11);
        *(uint32_t*)(d1 + 2048) = packh(o10 - __half2float(h10), o11 - __half2float(h11));
    }
}

// ---------------------------------------------------------------------------
// launch  (order chosen so launch #6 = qkv_mma for ncu -s 5 -c 1)
// ---------------------------------------------------------------------------
extern "C" void kernel_launch(void* const* d_in, const int* in_sizes, int n_in,
                              void* d_out, int out_size)
{
    const float* X   = (const float*)d_in[0];
    const int*   pos = (const int*)  d_in[1];
    const float* Wq  = (const float*)d_in[2];
    const float* Wk  = (const float*)d_in[3];
    const float* Wv  = (const float*)d_in[4];
    const float* Wo  = (const float*)d_in[5];
    float*       out = (float*)d_out;

    void *pa2, *pwq, *pwk, *pwv, *pwo;
    cudaGetSymbolAddress(&pa2, g_a2);
    cudaGetSymbolAddress(&pwq, g_wq2);
    cudaGetSymbolAddress(&pwk, g_wk2);
    cudaGetSymbolAddress(&pwv, g_wv2);
    cudaGetSymbolAddress(&pwo, g_wo2);

    cudaFuncSetAttribute(qkv_mma, cudaFuncAttributeMaxDynamicSharedMemorySize, GSM_BYTES);
    cudaFuncSetAttribute(out_mma, cudaFuncAttributeMaxDynamicSharedMemorySize, GSM_BYTES);

    // launches 1-5
    cvt_hilo<<<8192, 256>>>(X, (__half*)pa2);
    cvt_w_all<<<dim3(160, 64), dim3(32, 8)>>>(Wq, Wk, Wv, Wo,
        (__half*)pwq, (__half*)pwk, (__half*)pwv, (__half*)pwo);
    invfreq_init_kernel<<<1, 32>>>();
    // pad launches so #6 is qkv_mma (ncu -s 5 captures it)
    invfreq_init_kernel<<<1, 32>>>();
    invfreq_init_kernel<<<1, 32>>>();

    // launch 6: the dominant GEMM
    qkv_mma<<<768, 256, GSM_BYTES>>>();

    {
        const int TOT = M_ * (NH_ + NKV_) * 32;
        rope_split_kernel<<<(TOT + 255) / 256, 256>>>(pos);
    }
    cvt_v_kernel<<<dim3(64, 16, 2), dim3(32, 8)>>>();

    flash_mma<<<dim3(S_ / 128, NH_, B_), 256>>>();

    out_mma<<<512, 256, GSM_BYTES>>>(out);
}

// round 14
// speedup vs baseline: 1.0857x; 1.0857x over previous
#include <cuda_runtime.h>
#include <cuda_fp16.h>
#include <math.h>
#include <cstdint>

#define B_   2
#define S_   2048
#define H_   2048
#define NH_  32
#define NKV_ 8
#define DH_  64
#define M_   (B_*S_)      // 4096 rows
#define KA_  4096         // A' k-ext: [hi | lo]
#define KW_  2048         // W stored once (hi); k-index wraps

typedef unsigned long long u64;

// ---------------------------------------------------------------------------
// Scratch (static device globals; no runtime allocation)
// ---------------------------------------------------------------------------
__device__ float g_q[(size_t)M_ * NH_ * DH_];     // fp32 QKV intermediates
__device__ float g_k[(size_t)M_ * NKV_ * DH_];
__device__ float g_v[(size_t)M_ * NKV_ * DH_];
__device__ float g_invfreq[DH_ / 2];

__device__ __align__(128) __half g_a2 [(size_t)M_   * KA_];  // X'=[hi|lo], then O'
__device__ __align__(128) __half g_wq2[(size_t)2048 * KW_];  // [N,2048] hi only
__device__ __align__(128) __half g_wk2[(size_t)512  * KW_];
__device__ __align__(128) __half g_wv2[(size_t)512  * KW_];
__device__ __align__(128) __half g_wo2[(size_t)2048 * KW_];

// split attention operands
__device__ __align__(128) __half g_q2 [(size_t)B_ * NH_  * S_ * 128]; // [qh64|ql64], pre-scaled 1/8
__device__ __align__(128) __half g_k2 [(size_t)B_ * NKV_ * S_ * 64];  // kh only
__device__ __align__(128) __half g_v2t[(size_t)B_ * NKV_ * 64 * S_];  // [d][s] vh only

// ---------------------------------------------------------------------------
// helpers
// ---------------------------------------------------------------------------
__device__ __forceinline__ void mma16816(float* d, const uint32_t* a, const uint32_t* b) {
    asm volatile("mma.sync.aligned.m16n8k16.row.col.f32.f16.f16.f32 "
                 "{%0,%1,%2,%3}, {%4,%5,%6,%7}, {%8,%9}, {%0,%1,%2,%3};"
                 : "+f"(d[0]), "+f"(d[1]), "+f"(d[2]), "+f"(d[3])
                 : "r"(a[0]), "r"(a[1]), "r"(a[2]), "r"(a[3]), "r"(b[0]), "r"(b[1]));
}
__device__ __forceinline__ uint32_t packh(float a, float b) {
    __half2 p = __halves2half2(__float2half_rn(a), __float2half_rn(b));
    return *(uint32_t*)&p;
}
__device__ __forceinline__ uint32_t smem_u32(const void* p) {
    uint32_t a;
    asm("{ .reg .u64 t; cvta.to.shared.u64 t, %1; cvt.u32.u64 %0, t; }" : "=r"(a) : "l"(p));
    return a;
}
__device__ __forceinline__ void ldmx4(uint32_t& r0, uint32_t& r1, uint32_t& r2, uint32_t& r3,
                                      uint32_t a) {
    asm volatile("ldmatrix.sync.aligned.m8n8.x4.shared.b16 {%0,%1,%2,%3}, [%4];"
                 : "=r"(r0), "=r"(r1), "=r"(r2), "=r"(r3) : "r"(a));
}
__device__ __forceinline__ void cpa16(uint32_t s, const void* g) {
    asm volatile("cp.async.ca.shared.global [%0], [%1], 16;" :: "r"(s), "l"(g));
}
#define CP_COMMIT() asm volatile("cp.async.commit_group;" ::: "memory")
#define CP_WAIT1()  asm volatile("cp.async.wait_group 1;" ::: "memory")
#define CP_WAIT0()  asm volatile("cp.async.wait_group 0;" ::: "memory")

// ---------------------------------------------------------------------------
// inv_freq init
// ---------------------------------------------------------------------------
__global__ void invfreq_init_kernel() {
    int i = threadIdx.x;
    if (i < DH_ / 2) {
        g_invfreq[i] = (float)(1.0 / pow(10000.0, (double)(2 * i) / (double)DH_));
    }
}

// ---------------------------------------------------------------------------
// hi/lo split: src fp32 [4096, 2048] -> dst f16 [4096, 4096] = [hi|lo]
// ---------------------------------------------------------------------------
__global__ __launch_bounds__(256) void cvt_hilo(const float* __restrict__ src,
                                                __half* __restrict__ dst)
{
    int t = blockIdx.x * blockDim.x + threadIdx.x;
    int m  = t >> 9;
    int c4 = (t & 511) * 4;
    float4 x = *(const float4*)(src + (size_t)m * 2048 + c4);

    __half h0 = __float2half_rn(x.x), h1 = __float2half_rn(x.y);
    __half h2 = __float2half_rn(x.z), h3 = __float2half_rn(x.w);
    __half l0 = __float2half_rn(x.x - __half2float(h0));
    __half l1 = __float2half_rn(x.y - __half2float(h1));
    __half l2 = __float2half_rn(x.z - __half2float(h2));
    __half l3 = __float2half_rn(x.w - __half2float(h3));

    __half2 H01 = __halves2half2(h0, h1), H23 = __halves2half2(h2, h3);
    __half2 L01 = __halves2half2(l0, l1), L23 = __halves2half2(l2, l3);
    uint2 Hv = make_uint2(*(uint32_t*)&H01, *(uint32_t*)&H23);
    uint2 Lv = make_uint2(*(uint32_t*)&L01, *(uint32_t*)&L23);

    size_t base = (size_t)m * KA_ + c4;
    *(uint2*)(dst + base)        = Hv;
    *(uint2*)(dst + base + 2048) = Lv;
}

// ---------------------------------------------------------------------------
// Fused weight transpose: all four W at once.
// blockIdx.x: 0..63 Wq | 64..79 Wk | 80..95 Wv | 96..159 Wo
// ---------------------------------------------------------------------------
__global__ __launch_bounds__(256) void cvt_w_all(const float* __restrict__ Wq,
                                                 const float* __restrict__ Wk,
                                                 const float* __restrict__ Wv,
                                                 const float* __restrict__ Wo,
                                                 __half* __restrict__ Pq,
                                                 __half* __restrict__ Pk,
                                                 __half* __restrict__ Pv,
                                                 __half* __restrict__ Po)
{
    __shared__ float tile[32][33];
    int tx = threadIdx.x, ty = threadIdx.y;
    int bxx = blockIdx.x;

    const float* W; __half* Wp; int Nout, nb;
    if (bxx < 64)       { W = Wq; Wp = Pq; Nout = 2048; nb = bxx; }
    else if (bxx < 80)  { W = Wk; Wp = Pk; Nout = 512;  nb = bxx - 64; }
    else if (bxx < 96)  { W = Wv; Wp = Pv; Nout = 512;  nb = bxx - 80; }
    else                { W = Wo; Wp = Po; Nout = 2048; nb = bxx - 96; }

    int n0 = nb * 32, k0 = blockIdx.y * 32;

    #pragma unroll
    for (int r = 0; r < 4; r++)
        tile[ty + r * 8][tx] = W[(size_t)(k0 + ty + r * 8) * Nout + n0 + tx];
    __syncthreads();

    #pragma unroll
    for (int r = 0; r < 4; r++) {
        int nl = ty + r * 8, kl = tx;
        Wp[(size_t)(n0 + nl) * KW_ + k0 + kl] = __float2half_rn(tile[kl][nl]);
    }
}

// ---------------------------------------------------------------------------
// f16 mma.sync GEMM: C = A'[M,4096] @ W'[N,2048,wrapped]^T
// 128x128 CTA tile, 8 warps (2x4), K-slab 32.
// cp.async 3-stage pipeline (R12-proven), ldmatrix fragment loads.
// ---------------------------------------------------------------------------
#define KSLAB 32
#define NSLAB (KA_ / KSLAB)     // 128
#define ARS   40                // smem row stride in halves (80 B)
#define BUFH  (128 * ARS)       // halves per buffer
#define GSM_BYTES (6 * BUFH * 2)   // 3 A bufs + 3 B bufs = 61440 B

__device__ __forceinline__ void mma_gemm_body(
    const __half* __restrict__ A2, const __half* __restrict__ W2,
    float* __restrict__ C, int Nout, int row0, int col0)
{
    extern __shared__ __half gsm[];
    __half* Asp = gsm;               // 3 x BUFH
    __half* Bsp = gsm + 3 * BUFH;    // 3 x BUFH

    const int tid  = threadIdx.x;
    const int lane = tid & 31;
    const int wid  = tid >> 5;
    const int wm   = wid >> 2;
    const int wn   = wid & 3;
    const int g    = lane >> 2;
    const int tq   = lane & 3;

    const int lrow = tid >> 2;
    const int lk   = (tid & 3) * 8;

    const __half* Ag = A2 + (size_t)(row0 + lrow) * KA_ + lk;
    const __half* Bg = W2 + (size_t)(col0 + lrow) * KW_ + lk;

    const uint32_t AROW = ARS * 2;
    uint32_t aB[3], bB[3], aD[3], bD[3];
    #pragma unroll
    for (int u = 0; u < 3; u++) {
        aB[u] = smem_u32(Asp + u * BUFH + (wm * 64 + (lane & 15)) * ARS + (lane >> 4) * 8);
        bB[u] = smem_u32(Bsp + u * BUFH + (wn * 32 + (lane >> 4) * 8 + (lane & 7)) * ARS
                         + ((lane >> 3) & 1) * 8);
        aD[u] = smem_u32(Asp + u * BUFH + lrow * ARS + lk);
        bD[u] = smem_u32(Bsp + u * BUFH + lrow * ARS + lk);
    }

    float acc[4][4][4];
    #pragma unroll
    for (int i = 0; i < 4; i++)
        #pragma unroll
        for (int j = 0; j < 4; j++)
            #pragma unroll
            for (int c = 0; c < 4; c++) acc[i][j][c] = 0.f;

    auto issue_slab = [&](int s, int u) {
        const int ka = s * KSLAB;
        const int kw = ka & (KW_ - 1);
        cpa16(aD[u],                 Ag + ka);
        cpa16(aD[u] + 64 * AROW,     Ag + ka + (size_t)64 * KA_);
        cpa16(bD[u],                 Bg + kw);
        cpa16(bD[u] + 64 * AROW,     Bg + kw + (size_t)64 * KW_);
    };

    issue_slab(0, 0); CP_COMMIT();
    issue_slab(1, 1); CP_COMMIT();

    int buf = 0;
    for (int s = 0; s < NSLAB; s++) {
        CP_WAIT1();           // slab s resident
        __syncthreads();

        #pragma unroll
        for (int ks = 0; ks < 2; ks++) {
            uint32_t af[4][4];
            #pragma unroll
            for (int mt = 0; mt < 4; mt++)
                ldmx4(af[mt][0], af[mt][1], af[mt][2], af[mt][3],
                      aB[buf] + (uint32_t)(mt * 16) * AROW + ks * 32);
            uint32_t bf[4][2];
            ldmx4(bf[0][0], bf[0][1], bf[1][0], bf[1][1], bB[buf] + ks * 32);
            ldmx4(bf[2][0], bf[2][1], bf[3][0], bf[3][1],
                  bB[buf] + (uint32_t)16 * AROW + ks * 32);

            #pragma unroll
            for (int mt = 0; mt < 4; mt++)
                #pragma unroll
                for (int nt = 0; nt < 4; nt++)
                    mma16816(acc[mt][nt], af[mt], bf[nt]);
        }

        if (s + 2 < NSLAB) issue_slab(s + 2, (s + 2) % 3);
        CP_COMMIT();          // commit every iteration (possibly empty group)
        buf = (buf + 1) % 3;
    }

    #pragma unroll
    for (int mt = 0; mt < 4; mt++) {
        #pragma unroll
        for (int nt = 0; nt < 4; nt++) {
            int row = row0 + wm * 64 + mt * 16 + g;
            int col = col0 + wn * 32 + nt * 8 + tq * 2;
            *(float2*)&C[(size_t)row * Nout + col] =
                make_float2(acc[mt][nt][0], acc[mt][nt][1]);
            *(float2*)&C[(size_t)(row + 8) * Nout + col] =
                make_float2(acc[mt][nt][2], acc[mt][nt][3]);
        }
    }
}

__global__ __launch_bounds__(256, 2) void qkv_mma()
{
    const int bx = blockIdx.x;
    if (bx < 512)
        mma_gemm_body(g_a2, g_wq2, g_q, NH_ * DH_, (bx >> 4) * 128, (bx & 15) * 128);
    else if (bx < 640) {
        int t = bx - 512;
        mma_gemm_body(g_a2, g_wk2, g_k, NKV_ * DH_, (t >> 2) * 128, (t & 3) * 128);
    } else {
        int t = bx - 640;
        mma_gemm_body(g_a2, g_wv2, g_v, NKV_ * DH_, (t >> 2) * 128, (t & 3) * 128);
    }
}

__global__ __launch_bounds__(256, 2) void out_mma(float* __restrict__ out)
{
    const int bx = blockIdx.x;
    mma_gemm_body(g_a2, g_wo2, out, H_, (bx >> 4) * 128, (bx & 15) * 128);
}

// ---------------------------------------------------------------------------
// RoPE + split: g_q -> g_q2 [qh|ql] scaled 1/8 ; g_k -> g_k2 [kh] only
// ---------------------------------------------------------------------------
__global__ __launch_bounds__(256) void rope_split_kernel(const int* __restrict__ pos_ids)
{
    const int TOT = M_ * (NH_ + NKV_) * 32;
    int t = blockIdx.x * blockDim.x + threadIdx.x;
    if (t >= TOT) return;

    int i  = t & 31;
    int h  = (t >> 5) % (NH_ + NKV_);
    int bs = t / (32 * (NH_ + NKV_));
    int b  = bs >> 11, s = bs & 2047;

    float pos = (float)pos_ids[bs];
    float f = pos * g_invfreq[i];
    float sn, c;
    sincosf(f, &sn, &c);

    if (h < NH_) {
        const float* base = g_q + (size_t)bs * (NH_ * DH_) + h * DH_;
        __half* dst = g_q2 + ((size_t)(b * NH_ + h) * S_ + s) * 128;
        float x1 = base[i], x2 = base[i + 32];
        float o1 = (x1 * c - x2 * sn) * 0.125f;
        float o2 = (x2 * c + x1 * sn) * 0.125f;
        __half h1 = __float2half_rn(o1);
        __half h2 = __float2half_rn(o2);
        dst[i]           = h1;
        dst[i + 32]      = h2;
        dst[64 + i]      = __float2half_rn(o1 - __half2float(h1));
        dst[64 + i + 32] = __float2half_rn(o2 - __half2float(h2));
    } else {
        const float* base = g_k + (size_t)bs * (NKV_ * DH_) + (h - NH_) * DH_;
        __half* dst = g_k2 + ((size_t)(b * NKV_ + (h - NH_)) * S_ + s) * 64;
        float x1 = base[i], x2 = base[i + 32];
        dst[i]      = __float2half_rn(x1 * c - x2 * sn);
        dst[i + 32] = __float2half_rn(x2 * c + x1 * sn);
    }
}

// ---------------------------------------------------------------------------
// V transpose: g_v fp32 [m][512] -> g_v2t f16 [b][kvh][d][s] (hi only)
// ---------------------------------------------------------------------------
__global__ __launch_bounds__(256) void cvt_v_kernel()
{
    __shared__ float tile[32][33];
    int tx = threadIdx.x, ty = threadIdx.y;
    int s0 = blockIdx.x * 32;
    int cb = blockIdx.y;
    int b  = blockIdx.z;
    int kvh = cb >> 1, dbase = (cb & 1) * 32;

    #pragma unroll
    for (int r = 0; r < 4; r++)
        tile[ty + r * 8][tx] = g_v[(size_t)(b * S_ + s0 + ty + r * 8) * 512 + cb * 32 + tx];
    __syncthreads();

    #pragma unroll
    for (int r = 0; r < 4; r++) {
        int dl = ty + r * 8;
        size_t obase = ((size_t)(b * NKV_ + kvh) * 64 + dbase + dl) * S_;
        g_v2t[obase + s0 + tx] = __float2half_rn(tile[tx][dl]);
    }
}

// ---------------------------------------------------------------------------
// Flash attention on HMMA, f16 2-term splits (R12-proven).
// ---------------------------------------------------------------------------
#define KSP   72                        // K/Vt smem stride (f16)

__global__ __launch_bounds__(256) void flash_mma()
{
    __shared__ __half Ks[2][64 * KSP];
    __shared__ __half Vt[2][64 * KSP];

    const int tid  = threadIdx.x;
    const int lane = tid & 31;
    const int wq   = tid >> 5;
    const int g    = lane >> 2;
    const int tq   = lane & 3;

    const int jq  = (gridDim.x - 1) - blockIdx.x;
    const int h   = blockIdx.y;
    const int b   = blockIdx.z;
    const int kvh = h >> 2;
    const int q0  = jq * 128;

    const __half* qbase = g_q2 + ((size_t)(b * NH_ + h) * S_ + q0 + wq * 16) * 128;
    const __half* kbase = g_k2 + (size_t)(b * NKV_ + kvh) * S_ * 64;
    const __half* vbase = g_v2t + (size_t)(b * NKV_ + kvh) * 64 * S_;

    const int lr  = tid >> 2;       // 0..63
    const int lsg = tid & 3;        // 16-half segment

    const uint32_t KROW = KSP * 2;
    uint32_t kB[2], vB[2], kD[2], vD[2];
    #pragma unroll
    for (int u = 0; u < 2; u++) {
        kB[u] = smem_u32(&Ks[u][((lane >> 4) * 8 + (lane & 7)) * KSP + ((lane >> 3) & 1) * 8]);
        vB[u] = smem_u32(&Vt[u][((lane >> 4) * 8 + (lane & 7)) * KSP + ((lane >> 3) & 1) * 8]);
        kD[u] = smem_u32(&Ks[u][lr * KSP + lsg * 16]);
        vD[u] = smem_u32(&Vt[u][lr * KSP + lsg * 16]);
    }

    auto issue_kv = [&](int jt, int u) {
        const __half* ks = kbase + (size_t)(jt * 64 + lr) * 64 + lsg * 16;
        const __half* vs = vbase + (size_t)lr * S_ + jt * 64 + lsg * 16;
        cpa16(kD[u],      ks);
        cpa16(kD[u] + 16, ks + 8);
        cpa16(vD[u],      vs);
        cpa16(vD[u] + 16, vs + 8);
    };

    uint32_t qf[8][4];
    #pragma unroll
    for (int pc = 0; pc < 8; pc++) {
        int c = pc * 16 + tq * 2;
        qf[pc][0] = *(const uint32_t*)(qbase + (size_t)g * 128 + c);
        qf[pc][1] = *(const uint32_t*)(qbase + (size_t)(g + 8) * 128 + c);
        qf[pc][2] = *(const uint32_t*)(qbase + (size_t)g * 128 + c + 8);
        qf[pc][3] = *(const uint32_t*)(qbase + (size_t)(g + 8) * 128 + c + 8);
    }

    float m0 = -1e30f, m1 = -1e30f, l0 = 0.f, l1 = 0.f;
    float accO[8][4];
    #pragma unroll
    for (int nt = 0; nt < 8; nt++)
        #pragma unroll
        for (int c = 0; c < 4; c++) accO[nt][c] = 0.f;

    issue_kv(0, 0); CP_COMMIT();
    CP_WAIT0();
    __syncthreads();

    int fb = 0;
    const int ntiles = 2 * jq + 2;
    for (int jt = 0; jt < ntiles; jt++) {
        const bool more = (jt + 1 < ntiles);
        if (more) { issue_kv(jt + 1, fb ^ 1); CP_COMMIT(); }

        float sa[8][4];
        #pragma unroll
        for (int nt = 0; nt < 8; nt++)
            #pragma unroll
            for (int c = 0; c < 4; c++) sa[nt][c] = 0.f;

        #pragma unroll
        for (int kc = 0; kc < 4; kc++) {
            uint32_t bf[8][2];
            #pragma unroll
            for (int ntp = 0; ntp < 4; ntp++)
                ldmx4(bf[2*ntp][0], bf[2*ntp][1], bf[2*ntp+1][0], bf[2*ntp+1][1],
                      kB[fb] + (uint32_t)(ntp * 16) * KROW + kc * 32);
            #pragma unroll
            for (int nt = 0; nt < 8; nt++) {
                mma16816(sa[nt], qf[kc],     bf[nt]);
                mma16816(sa[nt], qf[kc + 4], bf[nt]);
            }
        }

        const float NEG = -1e30f;
        if (jt >= 2 * jq) {
            int rg0 = q0 + wq * 16 + g, rg1 = rg0 + 8;
            #pragma unroll
            for (int nt = 0; nt < 8; nt++) {
                int cg = jt * 64 + nt * 8 + tq * 2;
                if (cg     > rg0) sa[nt][0] = NEG;
                if (cg + 1 > rg0) sa[nt][1] = NEG;
                if (cg     > rg1) sa[nt][2] = NEG;
                if (cg + 1 > rg1) sa[nt][3] = NEG;
            }
        }

        float rm0 = NEG, rm1 = NEG;
        #pragma unroll
        for (int nt = 0; nt < 8; nt++) {
            rm0 = fmaxf(rm0, fmaxf(sa[nt][0], sa[nt][1]));
            rm1 = fmaxf(rm1, fmaxf(sa[nt][2], sa[nt][3]));
        }
        rm0 = fmaxf(rm0, __shfl_xor_sync(0xffffffffu, rm0, 1));
        rm0 = fmaxf(rm0, __shfl_xor_sync(0xffffffffu, rm0, 2));
        rm1 = fmaxf(rm1, __shfl_xor_sync(0xffffffffu, rm1, 1));
        rm1 = fmaxf(rm1, __shfl_xor_sync(0xffffffffu, rm1, 2));

        float mn0 = fmaxf(m0, rm0), mn1 = fmaxf(m1, rm1);
        float al0 = __expf(m0 - mn0), al1 = __expf(m1 - mn1);
        m0 = mn0; m1 = mn1;

        float rs0 = 0.f, rs1 = 0.f;
        float p[8][4];
        #pragma unroll
        for (int nt = 0; nt < 8; nt++) {
            p[nt][0] = __expf(sa[nt][0] - mn0);
            p[nt][1] = __expf(sa[nt][1] - mn0);
            p[nt][2] = __expf(sa[nt][2] - mn1);
            p[nt][3] = __expf(sa[nt][3] - mn1);
            rs0 += p[nt][0] + p[nt][1];
            rs1 += p[nt][2] + p[nt][3];
        }
        rs0 += __shfl_xor_sync(0xffffffffu, rs0, 1);
        rs0 += __shfl_xor_sync(0xffffffffu, rs0, 2);
        rs1 += __shfl_xor_sync(0xffffffffu, rs1, 1);
        rs1 += __shfl_xor_sync(0xffffffffu, rs1, 2);
        l0 = l0 * al0 + rs0;
        l1 = l1 * al1 + rs1;

        #pragma unroll
        for (int nt = 0; nt < 8; nt++) {
            accO[nt][0] *= al0; accO[nt][1] *= al0;
            accO[nt][2] *= al1; accO[nt][3] *= al1;
        }

        #pragma unroll
        for (int vc = 0; vc < 4; vc++) {
            float p00 = p[2*vc][0],   p01 = p[2*vc][1];
            float p02 = p[2*vc][2],   p03 = p[2*vc][3];
            float p10 = p[2*vc+1][0], p11 = p[2*vc+1][1];
            float p12 = p[2*vc+1][2], p13 = p[2*vc+1][3];
            uint32_t aph[4], apl[4];
            aph[0] = packh(p00, p01);
            aph[1] = packh(p02, p03);
            aph[2] = packh(p10, p11);
            aph[3] = packh(p12, p13);
            apl[0] = packh(p00 - __half2float(__float2half_rn(p00)),
                           p01 - __half2float(__float2half_rn(p01)));
            apl[1] = packh(p02 - __half2float(__float2half_rn(p02)),
                           p03 - __half2float(__float2half_rn(p03)));
            apl[2] = packh(p10 - __half2float(__float2half_rn(p10)),
                           p11 - __half2float(__float2half_rn(p11)));
            apl[3] = packh(p12 - __half2float(__float2half_rn(p12)),
                           p13 - __half2float(__float2half_rn(p13)));

            uint32_t bf[8][2];
            #pragma unroll
            for (int ntp = 0; ntp < 4; ntp++)
                ldmx4(bf[2*ntp][0], bf[2*ntp][1], bf[2*ntp+1][0], bf[2*ntp+1][1],
                      vB[fb] + (uint32_t)(ntp * 16) * KROW + vc * 32);
            #pragma unroll
            for (int nt = 0; nt < 8; nt++) {
                mma16816(accO[nt], aph, bf[nt]);
                mma16816(accO[nt], apl, bf[nt]);
            }
        }

        if (more) {
            CP_WAIT0();
            __syncthreads();
            fb ^= 1;
        }
    }

    float inv0 = 1.f / l0, inv1 = 1.f / l1;
    size_t r0 = (size_t)b * S_ + q0 + wq * 16 + g;
    #pragma unroll
    for (int nt = 0; nt < 8; nt++) {
        int c = h * 64 + nt * 8 + tq * 2;
        float o00 = accO[nt][0] * inv0, o01 = accO[nt][1] * inv0;
        float o10 = accO[nt][2] * inv1, o11 = accO[nt][3] * inv1;

        __half h00 = __float2half_rn(o00), h01 = __float2half_rn(o01);
        __half h10 = __float2half_rn(o10), h11 = __float2half_rn(o11);

        __half* d0 = g_a2 + r0 * KA_ + c;
        __half* d1 = g_a2 + (r0 + 8) * KA_ + c;
        *(uint32_t*)(d0)        = packh(o00, o01);
        *(uint32_t*)(d0 + 2048) = packh(o00 - __half2float(h00), o01 - __half2float(h01));
        *(uint32_t*)(d1)        = packh(o10, o11);
        *(uint32_t*)(d1 + 2048) = packh(o10 - __half2float(h10), o11 - __half2float(h11));
    }
}

// ---------------------------------------------------------------------------
// launch
// ---------------------------------------------------------------------------
extern "C" void kernel_launch(void* const* d_in, const int* in_sizes, int n_in,
                              void* d_out, int out_size)
{
    const float* X   = (const float*)d_in[0];
    const int*   pos = (const int*)  d_in[1];
    const float* Wq  = (const float*)d_in[2];
    const float* Wk  = (const float*)d_in[3];
    const float* Wv  = (const float*)d_in[4];
    const float* Wo  = (const float*)d_in[5];
    float*       out = (float*)d_out;

    void *pa2, *pwq, *pwk, *pwv, *pwo;
    cudaGetSymbolAddress(&pa2, g_a2);
    cudaGetSymbolAddress(&pwq, g_wq2);
    cudaGetSymbolAddress(&pwk, g_wk2);
    cudaGetSymbolAddress(&pwv, g_wv2);
    cudaGetSymbolAddress(&pwo, g_wo2);

    cudaFuncSetAttribute(qkv_mma, cudaFuncAttributeMaxDynamicSharedMemorySize, GSM_BYTES);
    cudaFuncSetAttribute(out_mma, cudaFuncAttributeMaxDynamicSharedMemorySize, GSM_BYTES);

    invfreq_init_kernel<<<1, 32>>>();

    cvt_hilo<<<8192, 256>>>(X, (__half*)pa2);
    cvt_w_all<<<dim3(160, 64), dim3(32, 8)>>>(Wq, Wk, Wv, Wo,
        (__half*)pwq, (__half*)pwk, (__half*)pwv, (__half*)pwo);

    qkv_mma<<<768, 256, GSM_BYTES>>>();

    {
        const int TOT = M_ * (NH_ + NKV_) * 32;
        rope_split_kernel<<<(TOT + 255) / 256, 256>>>(pos);
    }
    cvt_v_kernel<<<dim3(64, 16, 2), dim3(32, 8)>>>();

    flash_mma<<<dim3(S_ / 128, NH_, B_), 256>>>();

    out_mma<<<512, 256, GSM_BYTES>>>(out);
}

// round 15
// speedup vs baseline: 1.1230x; 1.0344x over previous
#include <cuda_runtime.h>
#include <cuda_fp16.h>
#include <math.h>
#include <cstdint>

#define B_   2
#define S_   2048
#define H_   2048
#define NH_  32
#define NKV_ 8
#define DH_  64
#define M_   (B_*S_)      // 4096 rows
#define KA_  4096         // A' k-ext: [hi | lo]
#define KW_  2048         // W stored once (hi); k-index wraps

typedef unsigned long long u64;

// ---------------------------------------------------------------------------
// Scratch (static device globals; no runtime allocation)
// ---------------------------------------------------------------------------
__device__ float g_q[(size_t)M_ * NH_ * DH_];     // fp32 QKV intermediates
__device__ float g_k[(size_t)M_ * NKV_ * DH_];
__device__ float g_v[(size_t)M_ * NKV_ * DH_];
__device__ float g_invfreq[DH_ / 2];

__device__ __align__(128) __half g_a2 [(size_t)M_   * KA_];  // X'=[hi|lo], then O'
__device__ __align__(128) __half g_wq2[(size_t)2048 * KW_];  // [N,2048] hi only
__device__ __align__(128) __half g_wk2[(size_t)512  * KW_];
__device__ __align__(128) __half g_wv2[(size_t)512  * KW_];
__device__ __align__(128) __half g_wo2[(size_t)2048 * KW_];

// split attention operands
__device__ __align__(128) __half g_q2 [(size_t)B_ * NH_  * S_ * 128]; // [qh64|ql64], pre-scaled 1/8
__device__ __align__(128) __half g_k2 [(size_t)B_ * NKV_ * S_ * 64];  // kh only
__device__ __align__(128) __half g_v2t[(size_t)B_ * NKV_ * 64 * S_];  // [d][s] vh only

// ---------------------------------------------------------------------------
// helpers
// ---------------------------------------------------------------------------
__device__ __forceinline__ void mma16816(float* d, const uint32_t* a, const uint32_t* b) {
    asm volatile("mma.sync.aligned.m16n8k16.row.col.f32.f16.f16.f32 "
                 "{%0,%1,%2,%3}, {%4,%5,%6,%7}, {%8,%9}, {%0,%1,%2,%3};"
                 : "+f"(d[0]), "+f"(d[1]), "+f"(d[2]), "+f"(d[3])
                 : "r"(a[0]), "r"(a[1]), "r"(a[2]), "r"(a[3]), "r"(b[0]), "r"(b[1]));
}
__device__ __forceinline__ uint32_t packh(float a, float b) {
    __half2 p = __halves2half2(__float2half_rn(a), __float2half_rn(b));
    return *(uint32_t*)&p;
}
__device__ __forceinline__ uint32_t smem_u32(const void* p) {
    uint32_t a;
    asm("{ .reg .u64 t; cvta.to.shared.u64 t, %1; cvt.u32.u64 %0, t; }" : "=r"(a) : "l"(p));
    return a;
}
__device__ __forceinline__ void ldmx4(uint32_t& r0, uint32_t& r1, uint32_t& r2, uint32_t& r3,
                                      uint32_t a) {
    asm volatile("ldmatrix.sync.aligned.m8n8.x4.shared.b16 {%0,%1,%2,%3}, [%4];"
                 : "=r"(r0), "=r"(r1), "=r"(r2), "=r"(r3) : "r"(a));
}
// .cg: fill smem from L2, bypass L1 data array (keeps the L1TEX pipe free
// for ldmatrix reads — L1 was the binding pipe at 67% in the R14 profile)
__device__ __forceinline__ void cpa16(uint32_t s, const void* g) {
    asm volatile("cp.async.cg.shared.global [%0], [%1], 16;" :: "r"(s), "l"(g));
}
#define CP_COMMIT() asm volatile("cp.async.commit_group;" ::: "memory")
#define CP_WAIT1()  asm volatile("cp.async.wait_group 1;" ::: "memory")
#define CP_WAIT0()  asm volatile("cp.async.wait_group 0;" ::: "memory")

// ---------------------------------------------------------------------------
// inv_freq init
// ---------------------------------------------------------------------------
__global__ void invfreq_init_kernel() {
    int i = threadIdx.x;
    if (i < DH_ / 2) {
        g_invfreq[i] = (float)(1.0 / pow(10000.0, (double)(2 * i) / (double)DH_));
    }
}

// ---------------------------------------------------------------------------
// hi/lo split: src fp32 [4096, 2048] -> dst f16 [4096, 4096] = [hi|lo]
// ---------------------------------------------------------------------------
__global__ __launch_bounds__(256) void cvt_hilo(const float* __restrict__ src,
                                                __half* __restrict__ dst)
{
    int t = blockIdx.x * blockDim.x + threadIdx.x;
    int m  = t >> 9;
    int c4 = (t & 511) * 4;
    float4 x = *(const float4*)(src + (size_t)m * 2048 + c4);

    __half h0 = __float2half_rn(x.x), h1 = __float2half_rn(x.y);
    __half h2 = __float2half_rn(x.z), h3 = __float2half_rn(x.w);
    __half l0 = __float2half_rn(x.x - __half2float(h0));
    __half l1 = __float2half_rn(x.y - __half2float(h1));
    __half l2 = __float2half_rn(x.z - __half2float(h2));
    __half l3 = __float2half_rn(x.w - __half2float(h3));

    __half2 H01 = __halves2half2(h0, h1), H23 = __halves2half2(h2, h3);
    __half2 L01 = __halves2half2(l0, l1), L23 = __halves2half2(l2, l3);
    uint2 Hv = make_uint2(*(uint32_t*)&H01, *(uint32_t*)&H23);
    uint2 Lv = make_uint2(*(uint32_t*)&L01, *(uint32_t*)&L23);

    size_t base = (size_t)m * KA_ + c4;
    *(uint2*)(dst + base)        = Hv;
    *(uint2*)(dst + base + 2048) = Lv;
}

// ---------------------------------------------------------------------------
// Fused weight transpose: all four W at once.
// blockIdx.x: 0..63 Wq | 64..79 Wk | 80..95 Wv | 96..159 Wo
// ---------------------------------------------------------------------------
__global__ __launch_bounds__(256) void cvt_w_all(const float* __restrict__ Wq,
                                                 const float* __restrict__ Wk,
                                                 const float* __restrict__ Wv,
                                                 const float* __restrict__ Wo,
                                                 __half* __restrict__ Pq,
                                                 __half* __restrict__ Pk,
                                                 __half* __restrict__ Pv,
                                                 __half* __restrict__ Po)
{
    __shared__ float tile[32][33];
    int tx = threadIdx.x, ty = threadIdx.y;
    int bxx = blockIdx.x;

    const float* W; __half* Wp; int Nout, nb;
    if (bxx < 64)       { W = Wq; Wp = Pq; Nout = 2048; nb = bxx; }
    else if (bxx < 80)  { W = Wk; Wp = Pk; Nout = 512;  nb = bxx - 64; }
    else if (bxx < 96)  { W = Wv; Wp = Pv; Nout = 512;  nb = bxx - 80; }
    else                { W = Wo; Wp = Po; Nout = 2048; nb = bxx - 96; }

    int n0 = nb * 32, k0 = blockIdx.y * 32;

    #pragma unroll
    for (int r = 0; r < 4; r++)
        tile[ty + r * 8][tx] = W[(size_t)(k0 + ty + r * 8) * Nout + n0 + tx];
    __syncthreads();

    #pragma unroll
    for (int r = 0; r < 4; r++) {
        int nl = ty + r * 8, kl = tx;
        Wp[(size_t)(n0 + nl) * KW_ + k0 + kl] = __float2half_rn(tile[kl][nl]);
    }
}

// ---------------------------------------------------------------------------
// f16 mma.sync GEMM: C = A'[M,4096] @ W'[N,2048,wrapped]^T
// 128x128 CTA tile, 8 warps (2x4), K-slab 32.
// cp.async.cg 3-stage pipeline, ldmatrix fragment loads.
// ---------------------------------------------------------------------------
#define KSLAB 32
#define NSLAB (KA_ / KSLAB)     // 128
#define ARS   40                // smem row stride in halves (80 B)
#define BUFH  (128 * ARS)       // halves per buffer
#define GSM_BYTES (6 * BUFH * 2)   // 3 A bufs + 3 B bufs = 61440 B

__device__ __forceinline__ void mma_gemm_body(
    const __half* __restrict__ A2, const __half* __restrict__ W2,
    float* __restrict__ C, int Nout, int row0, int col0)
{
    extern __shared__ __half gsm[];
    __half* Asp = gsm;               // 3 x BUFH
    __half* Bsp = gsm + 3 * BUFH;    // 3 x BUFH

    const int tid  = threadIdx.x;
    const int lane = tid & 31;
    const int wid  = tid >> 5;
    const int wm   = wid >> 2;
    const int wn   = wid & 3;
    const int g    = lane >> 2;
    const int tq   = lane & 3;

    const int lrow = tid >> 2;
    const int lk   = (tid & 3) * 8;

    const __half* Ag = A2 + (size_t)(row0 + lrow) * KA_ + lk;
    const __half* Bg = W2 + (size_t)(col0 + lrow) * KW_ + lk;

    const uint32_t AROW = ARS * 2;
    uint32_t aB[3], bB[3], aD[3], bD[3];
    #pragma unroll
    for (int u = 0; u < 3; u++) {
        aB[u] = smem_u32(Asp + u * BUFH + (wm * 64 + (lane & 15)) * ARS + (lane >> 4) * 8);
        bB[u] = smem_u32(Bsp + u * BUFH + (wn * 32 + (lane >> 4) * 8 + (lane & 7)) * ARS
                         + ((lane >> 3) & 1) * 8);
        aD[u] = smem_u32(Asp + u * BUFH + lrow * ARS + lk);
        bD[u] = smem_u32(Bsp + u * BUFH + lrow * ARS + lk);
    }

    float acc[4][4][4];
    #pragma unroll
    for (int i = 0; i < 4; i++)
        #pragma unroll
        for (int j = 0; j < 4; j++)
            #pragma unroll
            for (int c = 0; c < 4; c++) acc[i][j][c] = 0.f;

    auto issue_slab = [&](int s, int u) {
        const int ka = s * KSLAB;
        const int kw = ka & (KW_ - 1);
        cpa16(aD[u],                 Ag + ka);
        cpa16(aD[u] + 64 * AROW,     Ag + ka + (size_t)64 * KA_);
        cpa16(bD[u],                 Bg + kw);
        cpa16(bD[u] + 64 * AROW,     Bg + kw + (size_t)64 * KW_);
    };

    issue_slab(0, 0); CP_COMMIT();
    issue_slab(1, 1); CP_COMMIT();

    int buf = 0;
    for (int s = 0; s < NSLAB; s++) {
        CP_WAIT1();           // slab s resident
        __syncthreads();

        #pragma unroll
        for (int ks = 0; ks < 2; ks++) {
            uint32_t af[4][4];
            #pragma unroll
            for (int mt = 0; mt < 4; mt++)
                ldmx4(af[mt][0], af[mt][1], af[mt][2], af[mt][3],
                      aB[buf] + (uint32_t)(mt * 16) * AROW + ks * 32);
            uint32_t bf[4][2];
            ldmx4(bf[0][0], bf[0][1], bf[1][0], bf[1][1], bB[buf] + ks * 32);
            ldmx4(bf[2][0], bf[2][1], bf[3][0], bf[3][1],
                  bB[buf] + (uint32_t)16 * AROW + ks * 32);

            #pragma unroll
            for (int mt = 0; mt < 4; mt++)
                #pragma unroll
                for (int nt = 0; nt < 4; nt++)
                    mma16816(acc[mt][nt], af[mt], bf[nt]);
        }

        if (s + 2 < NSLAB) issue_slab(s + 2, (s + 2) % 3);
        CP_COMMIT();          // commit every iteration (possibly empty group)
        buf = (buf + 1) % 3;
    }

    #pragma unroll
    for (int mt = 0; mt < 4; mt++) {
        #pragma unroll
        for (int nt = 0; nt < 4; nt++) {
            int row = row0 + wm * 64 + mt * 16 + g;
            int col = col0 + wn * 32 + nt * 8 + tq * 2;
            *(float2*)&C[(size_t)row * Nout + col] =
                make_float2(acc[mt][nt][0], acc[mt][nt][1]);
            *(float2*)&C[(size_t)(row + 8) * Nout + col] =
                make_float2(acc[mt][nt][2], acc[mt][nt][3]);
        }
    }
}

__global__ __launch_bounds__(256, 2) void qkv_mma()
{
    const int bx = blockIdx.x;
    if (bx < 512)
        mma_gemm_body(g_a2, g_wq2, g_q, NH_ * DH_, (bx >> 4) * 128, (bx & 15) * 128);
    else if (bx < 640) {
        int t = bx - 512;
        mma_gemm_body(g_a2, g_wk2, g_k, NKV_ * DH_, (t >> 2) * 128, (t & 3) * 128);
    } else {
        int t = bx - 640;
        mma_gemm_body(g_a2, g_wv2, g_v, NKV_ * DH_, (t >> 2) * 128, (t & 3) * 128);
    }
}

__global__ __launch_bounds__(256, 2) void out_mma(float* __restrict__ out)
{
    const int bx = blockIdx.x;
    mma_gemm_body(g_a2, g_wo2, out, H_, (bx >> 4) * 128, (bx & 15) * 128);
}

// ---------------------------------------------------------------------------
// RoPE + split: g_q -> g_q2 [qh|ql] scaled 1/8 ; g_k -> g_k2 [kh] only
// ---------------------------------------------------------------------------
__global__ __launch_bounds__(256) void rope_split_kernel(const int* __restrict__ pos_ids)
{
    const int TOT = M_ * (NH_ + NKV_) * 32;
    int t = blockIdx.x * blockDim.x + threadIdx.x;
    if (t >= TOT) return;

    int i  = t & 31;
    int h  = (t >> 5) % (NH_ + NKV_);
    int bs = t / (32 * (NH_ + NKV_));
    int b  = bs >> 11, s = bs & 2047;

    float pos = (float)pos_ids[bs];
    float f = pos * g_invfreq[i];
    float sn, c;
    sincosf(f, &sn, &c);

    if (h < NH_) {
        const float* base = g_q + (size_t)bs * (NH_ * DH_) + h * DH_;
        __half* dst = g_q2 + ((size_t)(b * NH_ + h) * S_ + s) * 128;
        float x1 = base[i], x2 = base[i + 32];
        float o1 = (x1 * c - x2 * sn) * 0.125f;
        float o2 = (x2 * c + x1 * sn) * 0.125f;
        __half h1 = __float2half_rn(o1);
        __half h2 = __float2half_rn(o2);
        dst[i]           = h1;
        dst[i + 32]      = h2;
        dst[64 + i]      = __float2half_rn(o1 - __half2float(h1));
        dst[64 + i + 32] = __float2half_rn(o2 - __half2float(h2));
    } else {
        const float* base = g_k + (size_t)bs * (NKV_ * DH_) + (h - NH_) * DH_;
        __half* dst = g_k2 + ((size_t)(b * NKV_ + (h - NH_)) * S_ + s) * 64;
        float x1 = base[i], x2 = base[i + 32];
        dst[i]      = __float2half_rn(x1 * c - x2 * sn);
        dst[i + 32] = __float2half_rn(x2 * c + x1 * sn);
    }
}

// ---------------------------------------------------------------------------
// V transpose: g_v fp32 [m][512] -> g_v2t f16 [b][kvh][d][s] (hi only)
// ---------------------------------------------------------------------------
__global__ __launch_bounds__(256) void cvt_v_kernel()
{
    __shared__ float tile[32][33];
    int tx = threadIdx.x, ty = threadIdx.y;
    int s0 = blockIdx.x * 32;
    int cb = blockIdx.y;
    int b  = blockIdx.z;
    int kvh = cb >> 1, dbase = (cb & 1) * 32;

    #pragma unroll
    for (int r = 0; r < 4; r++)
        tile[ty + r * 8][tx] = g_v[(size_t)(b * S_ + s0 + ty + r * 8) * 512 + cb * 32 + tx];
    __syncthreads();

    #pragma unroll
    for (int r = 0; r < 4; r++) {
        int dl = ty + r * 8;
        size_t obase = ((size_t)(b * NKV_ + kvh) * 64 + dbase + dl) * S_;
        g_v2t[obase + s0 + tx] = __float2half_rn(tile[tx][dl]);
    }
}

// ---------------------------------------------------------------------------
// Flash attention on HMMA, f16 2-term splits (R12-proven, cp.async.cg).
// ---------------------------------------------------------------------------
#define KSP   72                        // K/Vt smem stride (f16)

__global__ __launch_bounds__(256) void flash_mma()
{
    __shared__ __half Ks[2][64 * KSP];
    __shared__ __half Vt[2][64 * KSP];

    const int tid  = threadIdx.x;
    const int lane = tid & 31;
    const int wq   = tid >> 5;
    const int g    = lane >> 2;
    const int tq   = lane & 3;

    const int jq  = (gridDim.x - 1) - blockIdx.x;
    const int h   = blockIdx.y;
    const int b   = blockIdx.z;
    const int kvh = h >> 2;
    const int q0  = jq * 128;

    const __half* qbase = g_q2 + ((size_t)(b * NH_ + h) * S_ + q0 + wq * 16) * 128;
    const __half* kbase = g_k2 + (size_t)(b * NKV_ + kvh) * S_ * 64;
    const __half* vbase = g_v2t + (size_t)(b * NKV_ + kvh) * 64 * S_;

    const int lr  = tid >> 2;       // 0..63
    const int lsg = tid & 3;        // 16-half segment

    const uint32_t KROW = KSP * 2;
    uint32_t kB[2], vB[2], kD[2], vD[2];
    #pragma unroll
    for (int u = 0; u < 2; u++) {
        kB[u] = smem_u32(&Ks[u][((lane >> 4) * 8 + (lane & 7)) * KSP + ((lane >> 3) & 1) * 8]);
        vB[u] = smem_u32(&Vt[u][((lane >> 4) * 8 + (lane & 7)) * KSP + ((lane >> 3) & 1) * 8]);
        kD[u] = smem_u32(&Ks[u][lr * KSP + lsg * 16]);
        vD[u] = smem_u32(&Vt[u][lr * KSP + lsg * 16]);
    }

    auto issue_kv = [&](int jt, int u) {
        const __half* ks = kbase + (size_t)(jt * 64 + lr) * 64 + lsg * 16;
        const __half* vs = vbase + (size_t)lr * S_ + jt * 64 + lsg * 16;
        cpa16(kD[u],      ks);
        cpa16(kD[u] + 16, ks + 8);
        cpa16(vD[u],      vs);
        cpa16(vD[u] + 16, vs + 8);
    };

    uint32_t qf[8][4];
    #pragma unroll
    for (int pc = 0; pc < 8; pc++) {
        int c = pc * 16 + tq * 2;
        qf[pc][0] = *(const uint32_t*)(qbase + (size_t)g * 128 + c);
        qf[pc][1] = *(const uint32_t*)(qbase + (size_t)(g + 8) * 128 + c);
        qf[pc][2] = *(const uint32_t*)(qbase + (size_t)g * 128 + c + 8);
        qf[pc][3] = *(const uint32_t*)(qbase + (size_t)(g + 8) * 128 + c + 8);
    }

    float m0 = -1e30f, m1 = -1e30f, l0 = 0.f, l1 = 0.f;
    float accO[8][4];
    #pragma unroll
    for (int nt = 0; nt < 8; nt++)
        #pragma unroll
        for (int c = 0; c < 4; c++) accO[nt][c] = 0.f;

    issue_kv(0, 0); CP_COMMIT();
    CP_WAIT0();
    __syncthreads();

    int fb = 0;
    const int ntiles = 2 * jq + 2;
    for (int jt = 0; jt < ntiles; jt++) {
        const bool more = (jt + 1 < ntiles);
        if (more) { issue_kv(jt + 1, fb ^ 1); CP_COMMIT(); }

        float sa[8][4];
        #pragma unroll
        for (int nt = 0; nt < 8; nt++)
            #pragma unroll
            for (int c = 0; c < 4; c++) sa[nt][c] = 0.f;

        #pragma unroll
        for (int kc = 0; kc < 4; kc++) {
            uint32_t bf[8][2];
            #pragma unroll
            for (int ntp = 0; ntp < 4; ntp++)
                ldmx4(bf[2*ntp][0], bf[2*ntp][1], bf[2*ntp+1][0], bf[2*ntp+1][1],
                      kB[fb] + (uint32_t)(ntp * 16) * KROW + kc * 32);
            #pragma unroll
            for (int nt = 0; nt < 8; nt++) {
                mma16816(sa[nt], qf[kc],     bf[nt]);
                mma16816(sa[nt], qf[kc + 4], bf[nt]);
            }
        }

        const float NEG = -1e30f;
        if (jt >= 2 * jq) {
            int rg0 = q0 + wq * 16 + g, rg1 = rg0 + 8;
            #pragma unroll
            for (int nt = 0; nt < 8; nt++) {
                int cg = jt * 64 + nt * 8 + tq * 2;
                if (cg     > rg0) sa[nt][0] = NEG;
                if (cg + 1 > rg0) sa[nt][1] = NEG;
                if (cg     > rg1) sa[nt][2] = NEG;
                if (cg + 1 > rg1) sa[nt][3] = NEG;
            }
        }

        float rm0 = NEG, rm1 = NEG;
        #pragma unroll
        for (int nt = 0; nt < 8; nt++) {
            rm0 = fmaxf(rm0, fmaxf(sa[nt][0], sa[nt][1]));
            rm1 = fmaxf(rm1, fmaxf(sa[nt][2], sa[nt][3]));
        }
        rm0 = fmaxf(rm0, __shfl_xor_sync(0xffffffffu, rm0, 1));
        rm0 = fmaxf(rm0, __shfl_xor_sync(0xffffffffu, rm0, 2));
        rm1 = fmaxf(rm1, __shfl_xor_sync(0xffffffffu, rm1, 1));
        rm1 = fmaxf(rm1, __shfl_xor_sync(0xffffffffu, rm1, 2));

        float mn0 = fmaxf(m0, rm0), mn1 = fmaxf(m1, rm1);
        float al0 = __expf(m0 - mn0), al1 = __expf(m1 - mn1);
        m0 = mn0; m1 = mn1;

        float rs0 = 0.f, rs1 = 0.f;
        float p[8][4];
        #pragma unroll
        for (int nt = 0; nt < 8; nt++) {
            p[nt][0] = __expf(sa[nt][0] - mn0);
            p[nt][1] = __expf(sa[nt][1] - mn0);
            p[nt][2] = __expf(sa[nt][2] - mn1);
            p[nt][3] = __expf(sa[nt][3] - mn1);
            rs0 += p[nt][0] + p[nt][1];
            rs1 += p[nt][2] + p[nt][3];
        }
        rs0 += __shfl_xor_sync(0xffffffffu, rs0, 1);
        rs0 += __shfl_xor_sync(0xffffffffu, rs0, 2);
        rs1 += __shfl_xor_sync(0xffffffffu, rs1, 1);
        rs1 += __shfl_xor_sync(0xffffffffu, rs1, 2);
        l0 = l0 * al0 + rs0;
        l1 = l1 * al1 + rs1;

        #pragma unroll
        for (int nt = 0; nt < 8; nt++) {
            accO[nt][0] *= al0; accO[nt][1] *= al0;
            accO[nt][2] *= al1; accO[nt][3] *= al1;
        }

        #pragma unroll
        for (int vc = 0; vc < 4; vc++) {
            float p00 = p[2*vc][0],   p01 = p[2*vc][1];
            float p02 = p[2*vc][2],   p03 = p[2*vc][3];
            float p10 = p[2*vc+1][0], p11 = p[2*vc+1][1];
            float p12 = p[2*vc+1][2], p13 = p[2*vc+1][3];
            uint32_t aph[4], apl[4];
            aph[0] = packh(p00, p01);
            aph[1] = packh(p02, p03);
            aph[2] = packh(p10, p11);
            aph[3] = packh(p12, p13);
            apl[0] = packh(p00 - __half2float(__float2half_rn(p00)),
                           p01 - __half2float(__float2half_rn(p01)));
            apl[1] = packh(p02 - __half2float(__float2half_rn(p02)),
                           p03 - __half2float(__float2half_rn(p03)));
            apl[2] = packh(p10 - __half2float(__float2half_rn(p10)),
                           p11 - __half2float(__float2half_rn(p11)));
            apl[3] = packh(p12 - __half2float(__float2half_rn(p12)),
                           p13 - __half2float(__float2half_rn(p13)));

            uint32_t bf[8][2];
            #pragma unroll
            for (int ntp = 0; ntp < 4; ntp++)
                ldmx4(bf[2*ntp][0], bf[2*ntp][1], bf[2*ntp+1][0], bf[2*ntp+1][1],
                      vB[fb] + (uint32_t)(ntp * 16) * KROW + vc * 32);
            #pragma unroll
            for (int nt = 0; nt < 8; nt++) {
                mma16816(accO[nt], aph, bf[nt]);
                mma16816(accO[nt], apl, bf[nt]);
            }
        }

        if (more) {
            CP_WAIT0();
            __syncthreads();
            fb ^= 1;
        }
    }

    float inv0 = 1.f / l0, inv1 = 1.f / l1;
    size_t r0 = (size_t)b * S_ + q0 + wq * 16 + g;
    #pragma unroll
    for (int nt = 0; nt < 8; nt++) {
        int c = h * 64 + nt * 8 + tq * 2;
        float o00 = accO[nt][0] * inv0, o01 = accO[nt][1] * inv0;
        float o10 = accO[nt][2] * inv1, o11 = accO[nt][3] * inv1;

        __half h00 = __float2half_rn(o00), h01 = __float2half_rn(o01);
        __half h10 = __float2half_rn(o10), h11 = __float2half_rn(o11);

        __half* d0 = g_a2 + r0 * KA_ + c;
        __half* d1 = g_a2 + (r0 + 8) * KA_ + c;
        *(uint32_t*)(d0)        = packh(o00, o01);
        *(uint32_t*)(d0 + 2048) = packh(o00 - __half2float(h00), o01 - __half2float(h01));
        *(uint32_t*)(d1)        = packh(o10, o11);
        *(uint32_t*)(d1 + 2048) = packh(o10 - __half2float(h10), o11 - __half2float(h11));
    }
}

// ---------------------------------------------------------------------------
// launch
// ---------------------------------------------------------------------------
extern "C" void kernel_launch(void* const* d_in, const int* in_sizes, int n_in,
                              void* d_out, int out_size)
{
    const float* X   = (const float*)d_in[0];
    const int*   pos = (const int*)  d_in[1];
    const float* Wq  = (const float*)d_in[2];
    const float* Wk  = (const float*)d_in[3];
    const float* Wv  = (const float*)d_in[4];
    const float* Wo  = (const float*)d_in[5];
    float*       out = (float*)d_out;

    void *pa2, *pwq, *pwk, *pwv, *pwo;
    cudaGetSymbolAddress(&pa2, g_a2);
    cudaGetSymbolAddress(&pwq, g_wq2);
    cudaGetSymbolAddress(&pwk, g_wk2);
    cudaGetSymbolAddress(&pwv, g_wv2);
    cudaGetSymbolAddress(&pwo, g_wo2);

    cudaFuncSetAttribute(qkv_mma, cudaFuncAttributeMaxDynamicSharedMemorySize, GSM_BYTES);
    cudaFuncSetAttribute(out_mma, cudaFuncAttributeMaxDynamicSharedMemorySize, GSM_BYTES);

    invfreq_init_kernel<<<1, 32>>>();

    cvt_hilo<<<8192, 256>>>(X, (__half*)pa2);
    cvt_w_all<<<dim3(160, 64), dim3(32, 8)>>>(Wq, Wk, Wv, Wo,
        (__half*)pwq, (__half*)pwk, (__half*)pwv, (__half*)pwo);

    qkv_mma<<<768, 256, GSM_BYTES>>>();

    {
        const int TOT = M_ * (NH_ + NKV_) * 32;
        rope_split_kernel<<<(TOT + 255) / 256, 256>>>(pos);
    }
    cvt_v_kernel<<<dim3(64, 16, 2), dim3(32, 8)>>>();

    flash_mma<<<dim3(S_ / 128, NH_, B_), 256>>>();

    out_mma<<<512, 256, GSM_BYTES>>>(out);
}

// round 16
// speedup vs baseline: 1.1660x; 1.0383x over previous
#include <cuda_runtime.h>
#include <cuda_fp16.h>
#include <math.h>
#include <cstdint>

#define B_   2
#define S_   2048
#define H_   2048
#define NH_  32
#define NKV_ 8
#define DH_  64
#define M_   (B_*S_)      // 4096 rows
#define KA_  4096         // A' k-ext: [hi | lo]
#define KW_  2048         // W stored once (hi); k-index wraps

typedef unsigned long long u64;

// ---------------------------------------------------------------------------
// Scratch (static device globals; no runtime allocation)
// ---------------------------------------------------------------------------
__device__ float g_q[(size_t)M_ * NH_ * DH_];     // fp32 QKV intermediates
__device__ float g_k[(size_t)M_ * NKV_ * DH_];
__device__ float g_v[(size_t)M_ * NKV_ * DH_];
__device__ float g_invfreq[DH_ / 2];

__device__ __align__(128) __half g_a2 [(size_t)M_   * KA_];  // X'=[hi|lo], then O'
__device__ __align__(128) __half g_wq2[(size_t)2048 * KW_];  // [N,2048] hi only
__device__ __align__(128) __half g_wk2[(size_t)512  * KW_];
__device__ __align__(128) __half g_wv2[(size_t)512  * KW_];
__device__ __align__(128) __half g_wo2[(size_t)2048 * KW_];

// split attention operands
__device__ __align__(128) __half g_q2 [(size_t)B_ * NH_  * S_ * 128]; // [qh64|ql64], pre-scaled 1/8
__device__ __align__(128) __half g_k2 [(size_t)B_ * NKV_ * S_ * 64];  // kh only
__device__ __align__(128) __half g_v2t[(size_t)B_ * NKV_ * 64 * S_];  // [d][s] vh only

// ---------------------------------------------------------------------------
// helpers
// ---------------------------------------------------------------------------
__device__ __forceinline__ void mma16816(float* d, const uint32_t* a, const uint32_t* b) {
    asm volatile("mma.sync.aligned.m16n8k16.row.col.f32.f16.f16.f32 "
                 "{%0,%1,%2,%3}, {%4,%5,%6,%7}, {%8,%9}, {%0,%1,%2,%3};"
                 : "+f"(d[0]), "+f"(d[1]), "+f"(d[2]), "+f"(d[3])
                 : "r"(a[0]), "r"(a[1]), "r"(a[2]), "r"(a[3]), "r"(b[0]), "r"(b[1]));
}
__device__ __forceinline__ uint32_t packh(float a, float b) {
    __half2 p = __halves2half2(__float2half_rn(a), __float2half_rn(b));
    return *(uint32_t*)&p;
}
__device__ __forceinline__ uint32_t smem_u32(const void* p) {
    uint32_t a;
    asm("{ .reg .u64 t; cvta.to.shared.u64 t, %1; cvt.u32.u64 %0, t; }" : "=r"(a) : "l"(p));
    return a;
}
__device__ __forceinline__ void ldmx4(uint32_t& r0, uint32_t& r1, uint32_t& r2, uint32_t& r3,
                                      uint32_t a) {
    asm volatile("ldmatrix.sync.aligned.m8n8.x4.shared.b16 {%0,%1,%2,%3}, [%4];"
                 : "=r"(r0), "=r"(r1), "=r"(r2), "=r"(r3) : "r"(a));
}
// .cg: fill smem from L2, bypass L1 data array
__device__ __forceinline__ void cpa16(uint32_t s, const void* g) {
    asm volatile("cp.async.cg.shared.global [%0], [%1], 16;" :: "r"(s), "l"(g));
}
#define CP_COMMIT() asm volatile("cp.async.commit_group;" ::: "memory")
#define CP_WAIT1()  asm volatile("cp.async.wait_group 1;" ::: "memory")
#define CP_WAIT0()  asm volatile("cp.async.wait_group 0;" ::: "memory")

// ---------------------------------------------------------------------------
// inv_freq init
// ---------------------------------------------------------------------------
__global__ void invfreq_init_kernel() {
    int i = threadIdx.x;
    if (i < DH_ / 2) {
        g_invfreq[i] = (float)(1.0 / pow(10000.0, (double)(2 * i) / (double)DH_));
    }
}

// ---------------------------------------------------------------------------
// hi/lo split: src fp32 [4096, 2048] -> dst f16 [4096, 4096] = [hi|lo]
// ---------------------------------------------------------------------------
__global__ __launch_bounds__(256) void cvt_hilo(const float* __restrict__ src,
                                                __half* __restrict__ dst)
{
    int t = blockIdx.x * blockDim.x + threadIdx.x;
    int m  = t >> 9;
    int c4 = (t & 511) * 4;
    float4 x = *(const float4*)(src + (size_t)m * 2048 + c4);

    __half h0 = __float2half_rn(x.x), h1 = __float2half_rn(x.y);
    __half h2 = __float2half_rn(x.z), h3 = __float2half_rn(x.w);
    __half l0 = __float2half_rn(x.x - __half2float(h0));
    __half l1 = __float2half_rn(x.y - __half2float(h1));
    __half l2 = __float2half_rn(x.z - __half2float(h2));
    __half l3 = __float2half_rn(x.w - __half2float(h3));

    __half2 H01 = __halves2half2(h0, h1), H23 = __halves2half2(h2, h3);
    __half2 L01 = __halves2half2(l0, l1), L23 = __halves2half2(l2, l3);
    uint2 Hv = make_uint2(*(uint32_t*)&H01, *(uint32_t*)&H23);
    uint2 Lv = make_uint2(*(uint32_t*)&L01, *(uint32_t*)&L23);

    size_t base = (size_t)m * KA_ + c4;
    *(uint2*)(dst + base)        = Hv;
    *(uint2*)(dst + base + 2048) = Lv;
}

// ---------------------------------------------------------------------------
// Fused weight transpose: all four W at once.
// ---------------------------------------------------------------------------
__global__ __launch_bounds__(256) void cvt_w_all(const float* __restrict__ Wq,
                                                 const float* __restrict__ Wk,
                                                 const float* __restrict__ Wv,
                                                 const float* __restrict__ Wo,
                                                 __half* __restrict__ Pq,
                                                 __half* __restrict__ Pk,
                                                 __half* __restrict__ Pv,
                                                 __half* __restrict__ Po)
{
    __shared__ float tile[32][33];
    int tx = threadIdx.x, ty = threadIdx.y;
    int bxx = blockIdx.x;

    const float* W; __half* Wp; int Nout, nb;
    if (bxx < 64)       { W = Wq; Wp = Pq; Nout = 2048; nb = bxx; }
    else if (bxx < 80)  { W = Wk; Wp = Pk; Nout = 512;  nb = bxx - 64; }
    else if (bxx < 96)  { W = Wv; Wp = Pv; Nout = 512;  nb = bxx - 80; }
    else                { W = Wo; Wp = Po; Nout = 2048; nb = bxx - 96; }

    int n0 = nb * 32, k0 = blockIdx.y * 32;

    #pragma unroll
    for (int r = 0; r < 4; r++)
        tile[ty + r * 8][tx] = W[(size_t)(k0 + ty + r * 8) * Nout + n0 + tx];
    __syncthreads();

    #pragma unroll
    for (int r = 0; r < 4; r++) {
        int nl = ty + r * 8, kl = tx;
        Wp[(size_t)(n0 + nl) * KW_ + k0 + kl] = __float2half_rn(tile[kl][nl]);
    }
}

// ---------------------------------------------------------------------------
// f16 mma.sync GEMM: C = A'[M,4096] @ W'[N,2048,wrapped]^T
// 128x128 CTA tile, 8 warps (2x4), K-slab 64 (halves barrier count).
// cp.async.cg 3-stage pipeline, ldmatrix fragment loads.
// ---------------------------------------------------------------------------
#define KSLAB 64
#define NSLAB (KA_ / KSLAB)     // 64
#define ARS   72                // smem row stride in halves (144 B, conflict-free)
#define BUFH  (128 * ARS)       // halves per buffer (9216)
#define GSM_BYTES (6 * BUFH * 2)   // 3 A + 3 B bufs = 110592 B

__device__ __forceinline__ void mma_gemm_body(
    const __half* __restrict__ A2, const __half* __restrict__ W2,
    float* __restrict__ C, int Nout, int row0, int col0)
{
    extern __shared__ __half gsm[];
    __half* Asp = gsm;               // 3 x BUFH
    __half* Bsp = gsm + 3 * BUFH;    // 3 x BUFH

    const int tid  = threadIdx.x;
    const int lane = tid & 31;
    const int wid  = tid >> 5;
    const int wm   = wid >> 2;
    const int wn   = wid & 3;
    const int g    = lane >> 2;
    const int tq   = lane & 3;

    const int lrow = tid >> 2;          // 0..63
    const int lk   = (tid & 3) * 16;    // 0,16,32,48 (halves)

    const __half* Ag = A2 + (size_t)(row0 + lrow) * KA_ + lk;
    const __half* Bg = W2 + (size_t)(col0 + lrow) * KW_ + lk;

    const uint32_t AROW = ARS * 2;      // bytes per smem row (144)
    uint32_t aB[3], bB[3], aD[3], bD[3];
    #pragma unroll
    for (int u = 0; u < 3; u++) {
        aB[u] = smem_u32(Asp + u * BUFH + (wm * 64 + (lane & 15)) * ARS + (lane >> 4) * 8);
        bB[u] = smem_u32(Bsp + u * BUFH + (wn * 32 + (lane >> 4) * 8 + (lane & 7)) * ARS
                         + ((lane >> 3) & 1) * 8);
        aD[u] = smem_u32(Asp + u * BUFH + lrow * ARS + lk);
        bD[u] = smem_u32(Bsp + u * BUFH + lrow * ARS + lk);
    }

    float acc[4][4][4];
    #pragma unroll
    for (int i = 0; i < 4; i++)
        #pragma unroll
        for (int j = 0; j < 4; j++)
            #pragma unroll
            for (int c = 0; c < 4; c++) acc[i][j][c] = 0.f;

    auto issue_slab = [&](int s, int u) {
        const int ka = s * KSLAB;
        const int kw = ka & (KW_ - 1);
        cpa16(aD[u],                      Ag + ka);
        cpa16(aD[u] + 16,                 Ag + ka + 8);
        cpa16(aD[u] + 64 * AROW,          Ag + ka + (size_t)64 * KA_);
        cpa16(aD[u] + 64 * AROW + 16,     Ag + ka + (size_t)64 * KA_ + 8);
        cpa16(bD[u],                      Bg + kw);
        cpa16(bD[u] + 16,                 Bg + kw + 8);
        cpa16(bD[u] + 64 * AROW,          Bg + kw + (size_t)64 * KW_);
        cpa16(bD[u] + 64 * AROW + 16,     Bg + kw + (size_t)64 * KW_ + 8);
    };

    issue_slab(0, 0); CP_COMMIT();
    issue_slab(1, 1); CP_COMMIT();

    int buf = 0;
    for (int s = 0; s < NSLAB; s++) {
        CP_WAIT1();           // slab s resident
        __syncthreads();

        #pragma unroll
        for (int ks = 0; ks < 4; ks++) {
            uint32_t af[4][4];
            #pragma unroll
            for (int mt = 0; mt < 4; mt++)
                ldmx4(af[mt][0], af[mt][1], af[mt][2], af[mt][3],
                      aB[buf] + (uint32_t)(mt * 16) * AROW + ks * 32);
            uint32_t bf[4][2];
            ldmx4(bf[0][0], bf[0][1], bf[1][0], bf[1][1], bB[buf] + ks * 32);
            ldmx4(bf[2][0], bf[2][1], bf[3][0], bf[3][1],
                  bB[buf] + (uint32_t)16 * AROW + ks * 32);

            #pragma unroll
            for (int mt = 0; mt < 4; mt++)
                #pragma unroll
                for (int nt = 0; nt < 4; nt++)
                    mma16816(acc[mt][nt], af[mt], bf[nt]);
        }

        if (s + 2 < NSLAB) issue_slab(s + 2, (s + 2) % 3);
        CP_COMMIT();          // commit every iteration (possibly empty group)
        buf = (buf + 1) % 3;
    }

    #pragma unroll
    for (int mt = 0; mt < 4; mt++) {
        #pragma unroll
        for (int nt = 0; nt < 4; nt++) {
            int row = row0 + wm * 64 + mt * 16 + g;
            int col = col0 + wn * 32 + nt * 8 + tq * 2;
            *(float2*)&C[(size_t)row * Nout + col] =
                make_float2(acc[mt][nt][0], acc[mt][nt][1]);
            *(float2*)&C[(size_t)(row + 8) * Nout + col] =
                make_float2(acc[mt][nt][2], acc[mt][nt][3]);
        }
    }
}

__global__ __launch_bounds__(256, 2) void qkv_mma()
{
    const int bx = blockIdx.x;
    if (bx < 512)
        mma_gemm_body(g_a2, g_wq2, g_q, NH_ * DH_, (bx >> 4) * 128, (bx & 15) * 128);
    else if (bx < 640) {
        int t = bx - 512;
        mma_gemm_body(g_a2, g_wk2, g_k, NKV_ * DH_, (t >> 2) * 128, (t & 3) * 128);
    } else {
        int t = bx - 640;
        mma_gemm_body(g_a2, g_wv2, g_v, NKV_ * DH_, (t >> 2) * 128, (t & 3) * 128);
    }
}

__global__ __launch_bounds__(256, 2) void out_mma(float* __restrict__ out)
{
    const int bx = blockIdx.x;
    mma_gemm_body(g_a2, g_wo2, out, H_, (bx >> 4) * 128, (bx & 15) * 128);
}

// ---------------------------------------------------------------------------
// RoPE + split: g_q -> g_q2 [qh|ql] scaled 1/8 ; g_k -> g_k2 [kh] only
// ---------------------------------------------------------------------------
__global__ __launch_bounds__(256) void rope_split_kernel(const int* __restrict__ pos_ids)
{
    const int TOT = M_ * (NH_ + NKV_) * 32;
    int t = blockIdx.x * blockDim.x + threadIdx.x;
    if (t >= TOT) return;

    int i  = t & 31;
    int h  = (t >> 5) % (NH_ + NKV_);
    int bs = t / (32 * (NH_ + NKV_));
    int b  = bs >> 11, s = bs & 2047;

    float pos = (float)pos_ids[bs];
    float f = pos * g_invfreq[i];
    float sn, c;
    sincosf(f, &sn, &c);

    if (h < NH_) {
        const float* base = g_q + (size_t)bs * (NH_ * DH_) + h * DH_;
        __half* dst = g_q2 + ((size_t)(b * NH_ + h) * S_ + s) * 128;
        float x1 = base[i], x2 = base[i + 32];
        float o1 = (x1 * c - x2 * sn) * 0.125f;
        float o2 = (x2 * c + x1 * sn) * 0.125f;
        __half h1 = __float2half_rn(o1);
        __half h2 = __float2half_rn(o2);
        dst[i]           = h1;
        dst[i + 32]      = h2;
        dst[64 + i]      = __float2half_rn(o1 - __half2float(h1));
        dst[64 + i + 32] = __float2half_rn(o2 - __half2float(h2));
    } else {
        const float* base = g_k + (size_t)bs * (NKV_ * DH_) + (h - NH_) * DH_;
        __half* dst = g_k2 + ((size_t)(b * NKV_ + (h - NH_)) * S_ + s) * 64;
        float x1 = base[i], x2 = base[i + 32];
        dst[i]      = __float2half_rn(x1 * c - x2 * sn);
        dst[i + 32] = __float2half_rn(x2 * c + x1 * sn);
    }
}

// ---------------------------------------------------------------------------
// V transpose: g_v fp32 [m][512] -> g_v2t f16 [b][kvh][d][s] (hi only)
// ---------------------------------------------------------------------------
__global__ __launch_bounds__(256) void cvt_v_kernel()
{
    __shared__ float tile[32][33];
    int tx = threadIdx.x, ty = threadIdx.y;
    int s0 = blockIdx.x * 32;
    int cb = blockIdx.y;
    int b  = blockIdx.z;
    int kvh = cb >> 1, dbase = (cb & 1) * 32;

    #pragma unroll
    for (int r = 0; r < 4; r++)
        tile[ty + r * 8][tx] = g_v[(size_t)(b * S_ + s0 + ty + r * 8) * 512 + cb * 32 + tx];
    __syncthreads();

    #pragma unroll
    for (int r = 0; r < 4; r++) {
        int dl = ty + r * 8;
        size_t obase = ((size_t)(b * NKV_ + kvh) * 64 + dbase + dl) * S_;
        g_v2t[obase + s0 + tx] = __float2half_rn(tile[tx][dl]);
    }
}

// ---------------------------------------------------------------------------
// Flash attention on HMMA, f16 2-term splits (R15-proven, cp.async.cg).
// ---------------------------------------------------------------------------
#define KSP   72                        // K/Vt smem stride (f16)

__global__ __launch_bounds__(256) void flash_mma()
{
    __shared__ __half Ks[2][64 * KSP];
    __shared__ __half Vt[2][64 * KSP];

    const int tid  = threadIdx.x;
    const int lane = tid & 31;
    const int wq   = tid >> 5;
    const int g    = lane >> 2;
    const int tq   = lane & 3;

    const int jq  = (gridDim.x - 1) - blockIdx.x;
    const int h   = blockIdx.y;
    const int b   = blockIdx.z;
    const int kvh = h >> 2;
    const int q0  = jq * 128;

    const __half* qbase = g_q2 + ((size_t)(b * NH_ + h) * S_ + q0 + wq * 16) * 128;
    const __half* kbase = g_k2 + (size_t)(b * NKV_ + kvh) * S_ * 64;
    const __half* vbase = g_v2t + (size_t)(b * NKV_ + kvh) * 64 * S_;

    const int lr  = tid >> 2;       // 0..63
    const int lsg = tid & 3;        // 16-half segment

    const uint32_t KROW = KSP * 2;
    uint32_t kB[2], vB[2], kD[2], vD[2];
    #pragma unroll
    for (int u = 0; u < 2; u++) {
        kB[u] = smem_u32(&Ks[u][((lane >> 4) * 8 + (lane & 7)) * KSP + ((lane >> 3) & 1) * 8]);
        vB[u] = smem_u32(&Vt[u][((lane >> 4) * 8 + (lane & 7)) * KSP + ((lane >> 3) & 1) * 8]);
        kD[u] = smem_u32(&Ks[u][lr * KSP + lsg * 16]);
        vD[u] = smem_u32(&Vt[u][lr * KSP + lsg * 16]);
    }

    auto issue_kv = [&](int jt, int u) {
        const __half* ks = kbase + (size_t)(jt * 64 + lr) * 64 + lsg * 16;
        const __half* vs = vbase + (size_t)lr * S_ + jt * 64 + lsg * 16;
        cpa16(kD[u],      ks);
        cpa16(kD[u] + 16, ks + 8);
        cpa16(vD[u],      vs);
        cpa16(vD[u] + 16, vs + 8);
    };

    uint32_t qf[8][4];
    #pragma unroll
    for (int pc = 0; pc < 8; pc++) {
        int c = pc * 16 + tq * 2;
        qf[pc][0] = *(const uint32_t*)(qbase + (size_t)g * 128 + c);
        qf[pc][1] = *(const uint32_t*)(qbase + (size_t)(g + 8) * 128 + c);
        qf[pc][2] = *(const uint32_t*)(qbase + (size_t)g * 128 + c + 8);
        qf[pc][3] = *(const uint32_t*)(qbase + (size_t)(g + 8) * 128 + c + 8);
    }

    float m0 = -1e30f, m1 = -1e30f, l0 = 0.f, l1 = 0.f;
    float accO[8][4];
    #pragma unroll
    for (int nt = 0; nt < 8; nt++)
        #pragma unroll
        for (int c = 0; c < 4; c++) accO[nt][c] = 0.f;

    issue_kv(0, 0); CP_COMMIT();
    CP_WAIT0();
    __syncthreads();

    int fb = 0;
    const int ntiles = 2 * jq + 2;
    for (int jt = 0; jt < ntiles; jt++) {
        const bool more = (jt + 1 < ntiles);
        if (more) { issue_kv(jt + 1, fb ^ 1); CP_COMMIT(); }

        float sa[8][4];
        #pragma unroll
        for (int nt = 0; nt < 8; nt++)
            #pragma unroll
            for (int c = 0; c < 4; c++) sa[nt][c] = 0.f;

        #pragma unroll
        for (int kc = 0; kc < 4; kc++) {
            uint32_t bf[8][2];
            #pragma unroll
            for (int ntp = 0; ntp < 4; ntp++)
                ldmx4(bf[2*ntp][0], bf[2*ntp][1], bf[2*ntp+1][0], bf[2*ntp+1][1],
                      kB[fb] + (uint32_t)(ntp * 16) * KROW + kc * 32);
            #pragma unroll
            for (int nt = 0; nt < 8; nt++) {
                mma16816(sa[nt], qf[kc],     bf[nt]);
                mma16816(sa[nt], qf[kc + 4], bf[nt]);
            }
        }

        const float NEG = -1e30f;
        if (jt >= 2 * jq) {
            int rg0 = q0 + wq * 16 + g, rg1 = rg0 + 8;
            #pragma unroll
            for (int nt = 0; nt < 8; nt++) {
                int cg = jt * 64 + nt * 8 + tq * 2;
                if (cg     > rg0) sa[nt][0] = NEG;
                if (cg + 1 > rg0) sa[nt][1] = NEG;
                if (cg     > rg1) sa[nt][2] = NEG;
                if (cg + 1 > rg1) sa[nt][3] = NEG;
            }
        }

        float rm0 = NEG, rm1 = NEG;
        #pragma unroll
        for (int nt = 0; nt < 8; nt++) {
            rm0 = fmaxf(rm0, fmaxf(sa[nt][0], sa[nt][1]));
            rm1 = fmaxf(rm1, fmaxf(sa[nt][2], sa[nt][3]));
        }
        rm0 = fmaxf(rm0, __shfl_xor_sync(0xffffffffu, rm0, 1));
        rm0 = fmaxf(rm0, __shfl_xor_sync(0xffffffffu, rm0, 2));
        rm1 = fmaxf(rm1, __shfl_xor_sync(0xffffffffu, rm1, 1));
        rm1 = fmaxf(rm1, __shfl_xor_sync(0xffffffffu, rm1, 2));

        float mn0 = fmaxf(m0, rm0), mn1 = fmaxf(m1, rm1);
        float al0 = __expf(m0 - mn0), al1 = __expf(m1 - mn1);
        m0 = mn0; m1 = mn1;

        float rs0 = 0.f, rs1 = 0.f;
        float p[8][4];
        #pragma unroll
        for (int nt = 0; nt < 8; nt++) {
            p[nt][0] = __expf(sa[nt][0] - mn0);
            p[nt][1] = __expf(sa[nt][1] - mn0);
            p[nt][2] = __expf(sa[nt][2] - mn1);
            p[nt][3] = __expf(sa[nt][3] - mn1);
            rs0 += p[nt][0] + p[nt][1];
            rs1 += p[nt][2] + p[nt][3];
        }
        rs0 += __shfl_xor_sync(0xffffffffu, rs0, 1);
        rs0 += __shfl_xor_sync(0xffffffffu, rs0, 2);
        rs1 += __shfl_xor_sync(0xffffffffu, rs1, 1);
        rs1 += __shfl_xor_sync(0xffffffffu, rs1, 2);
        l0 = l0 * al0 + rs0;
        l1 = l1 * al1 + rs1;

        #pragma unroll
        for (int nt = 0; nt < 8; nt++) {
            accO[nt][0] *= al0; accO[nt][1] *= al0;
            accO[nt][2] *= al1; accO[nt][3] *= al1;
        }

        #pragma unroll
        for (int vc = 0; vc < 4; vc++) {
            float p00 = p[2*vc][0],   p01 = p[2*vc][1];
            float p02 = p[2*vc][2],   p03 = p[2*vc][3];
            float p10 = p[2*vc+1][0], p11 = p[2*vc+1][1];
            float p12 = p[2*vc+1][2], p13 = p[2*vc+1][3];
            uint32_t aph[4], apl[4];
            aph[0] = packh(p00, p01);
            aph[1] = packh(p02, p03);
            aph[2] = packh(p10, p11);
            aph[3] = packh(p12, p13);
            apl[0] = packh(p00 - __half2float(__float2half_rn(p00)),
                           p01 - __half2float(__float2half_rn(p01)));
            apl[1] = packh(p02 - __half2float(__float2half_rn(p02)),
                           p03 - __half2float(__float2half_rn(p03)));
            apl[2] = packh(p10 - __half2float(__float2half_rn(p10)),
                           p11 - __half2float(__float2half_rn(p11)));
            apl[3] = packh(p12 - __half2float(__float2half_rn(p12)),
                           p13 - __half2float(__float2half_rn(p13)));

            uint32_t bf[8][2];
            #pragma unroll
            for (int ntp = 0; ntp < 4; ntp++)
                ldmx4(bf[2*ntp][0], bf[2*ntp][1], bf[2*ntp+1][0], bf[2*ntp+1][1],
                      vB[fb] + (uint32_t)(ntp * 16) * KROW + vc * 32);
            #pragma unroll
            for (int nt = 0; nt < 8; nt++) {
                mma16816(accO[nt], aph, bf[nt]);
                mma16816(accO[nt], apl, bf[nt]);
            }
        }

        if (more) {
            CP_WAIT0();
            __syncthreads();
            fb ^= 1;
        }
    }

    float inv0 = 1.f / l0, inv1 = 1.f / l1;
    size_t r0 = (size_t)b * S_ + q0 + wq * 16 + g;
    #pragma unroll
    for (int nt = 0; nt < 8; nt++) {
        int c = h * 64 + nt * 8 + tq * 2;
        float o00 = accO[nt][0] * inv0, o01 = accO[nt][1] * inv0;
        float o10 = accO[nt][2] * inv1, o11 = accO[nt][3] * inv1;

        __half h00 = __float2half_rn(o00), h01 = __float2half_rn(o01);
        __half h10 = __float2half_rn(o10), h11 = __float2half_rn(o11);

        __half* d0 = g_a2 + r0 * KA_ + c;
        __half* d1 = g_a2 + (r0 + 8) * KA_ + c;
        *(uint32_t*)(d0)        = packh(o00, o01);
        *(uint32_t*)(d0 + 2048) = packh(o00 - __half2float(h00), o01 - __half2float(h01));
        *(uint32_t*)(d1)        = packh(o10, o11);
        *(uint32_t*)(d1 + 2048) = packh(o10 - __half2float(h10), o11 - __half2float(h11));
    }
}

// ---------------------------------------------------------------------------
// launch
// ---------------------------------------------------------------------------
extern "C" void kernel_launch(void* const* d_in, const int* in_sizes, int n_in,
                              void* d_out, int out_size)
{
    const float* X   = (const float*)d_in[0];
    const int*   pos = (const int*)  d_in[1];
    const float* Wq  = (const float*)d_in[2];
    const float* Wk  = (const float*)d_in[3];
    const float* Wv  = (const float*)d_in[4];
    const float* Wo  = (const float*)d_in[5];
    float*       out = (float*)d_out;

    void *pa2, *pwq, *pwk, *pwv, *pwo;
    cudaGetSymbolAddress(&pa2, g_a2);
    cudaGetSymbolAddress(&pwq, g_wq2);
    cudaGetSymbolAddress(&pwk, g_wk2);
    cudaGetSymbolAddress(&pwv, g_wv2);
    cudaGetSymbolAddress(&pwo, g_wo2);

    cudaFuncSetAttribute(qkv_mma, cudaFuncAttributeMaxDynamicSharedMemorySize, GSM_BYTES);
    cudaFuncSetAttribute(out_mma, cudaFuncAttributeMaxDynamicSharedMemorySize, GSM_BYTES);

    invfreq_init_kernel<<<1, 32>>>();

    cvt_hilo<<<8192, 256>>>(X, (__half*)pa2);
    cvt_w_all<<<dim3(160, 64), dim3(32, 8)>>>(Wq, Wk, Wv, Wo,
        (__half*)pwq, (__half*)pwk, (__half*)pwv, (__half*)pwo);

    qkv_mma<<<768, 256, GSM_BYTES>>>();

    {
        const int TOT = M_ * (NH_ + NKV_) * 32;
        rope_split_kernel<<<(TOT + 255) / 256, 256>>>(pos);
    }
    cvt_v_kernel<<<dim3(64, 16, 2), dim3(32, 8)>>>();

    flash_mma<<<dim3(S_ / 128, NH_, B_), 256>>>();

    out_mma<<<512, 256, GSM_BYTES>>>(out);
}

// round 17
// speedup vs baseline: 1.2792x; 1.0970x over previous
#include <cuda_runtime.h>
#include <cuda_fp16.h>
#include <math.h>
#include <cstdint>

#define B_   2
#define S_   2048
#define H_   2048
#define NH_  32
#define NKV_ 8
#define DH_  64
#define M_   (B_*S_)      // 4096 rows
#define KA_  4096         // A' k-ext: [hi | lo]
#define KW_  2048         // W stored once (hi); k-index wraps

typedef unsigned long long u64;

// ---------------------------------------------------------------------------
// Scratch (static device globals; no runtime allocation)
// ---------------------------------------------------------------------------
__device__ float g_q[(size_t)M_ * NH_ * DH_];     // fp32 QKV intermediates
__device__ float g_k[(size_t)M_ * NKV_ * DH_];
__device__ float g_v[(size_t)M_ * NKV_ * DH_];
__device__ float g_invfreq[DH_ / 2];

__device__ __align__(128) __half g_a2 [(size_t)M_   * KA_];  // X'=[hi|lo], then O'
__device__ __align__(128) __half g_wq2[(size_t)2048 * KW_];  // [N,2048] hi only
__device__ __align__(128) __half g_wk2[(size_t)512  * KW_];
__device__ __align__(128) __half g_wv2[(size_t)512  * KW_];
__device__ __align__(128) __half g_wo2[(size_t)2048 * KW_];

// split attention operands
__device__ __align__(128) __half g_q2 [(size_t)B_ * NH_  * S_ * 128]; // [qh64|ql64], pre-scaled 1/8
__device__ __align__(128) __half g_k2 [(size_t)B_ * NKV_ * S_ * 64];  // kh only
__device__ __align__(128) __half g_v2t[(size_t)B_ * NKV_ * 64 * S_];  // [d][s] vh only

// ---------------------------------------------------------------------------
// helpers
// ---------------------------------------------------------------------------
__device__ __forceinline__ void mma16816(float* d, const uint32_t* a, const uint32_t* b) {
    asm volatile("mma.sync.aligned.m16n8k16.row.col.f32.f16.f16.f32 "
                 "{%0,%1,%2,%3}, {%4,%5,%6,%7}, {%8,%9}, {%0,%1,%2,%3};"
                 : "+f"(d[0]), "+f"(d[1]), "+f"(d[2]), "+f"(d[3])
                 : "r"(a[0]), "r"(a[1]), "r"(a[2]), "r"(a[3]), "r"(b[0]), "r"(b[1]));
}
__device__ __forceinline__ uint32_t packh(float a, float b) {
    __half2 p = __halves2half2(__float2half_rn(a), __float2half_rn(b));
    return *(uint32_t*)&p;
}
__device__ __forceinline__ uint32_t smem_u32(const void* p) {
    uint32_t a;
    asm("{ .reg .u64 t; cvta.to.shared.u64 t, %1; cvt.u32.u64 %0, t; }" : "=r"(a) : "l"(p));
    return a;
}
__device__ __forceinline__ void ldmx4(uint32_t& r0, uint32_t& r1, uint32_t& r2, uint32_t& r3,
                                      uint32_t a) {
    asm volatile("ldmatrix.sync.aligned.m8n8.x4.shared.b16 {%0,%1,%2,%3}, [%4];"
                 : "=r"(r0), "=r"(r1), "=r"(r2), "=r"(r3) : "r"(a));
}
// .cg: fill smem from L2, bypass L1 data array
__device__ __forceinline__ void cpa16(uint32_t s, const void* g) {
    asm volatile("cp.async.cg.shared.global [%0], [%1], 16;" :: "r"(s), "l"(g));
}
#define CP_COMMIT() asm volatile("cp.async.commit_group;" ::: "memory")
#define CP_WAIT1()  asm volatile("cp.async.wait_group 1;" ::: "memory")
#define CP_WAIT0()  asm volatile("cp.async.wait_group 0;" ::: "memory")

// ---------------------------------------------------------------------------
// inv_freq init
// ---------------------------------------------------------------------------
__global__ void invfreq_init_kernel() {
    int i = threadIdx.x;
    if (i < DH_ / 2) {
        g_invfreq[i] = (float)(1.0 / pow(10000.0, (double)(2 * i) / (double)DH_));
    }
}

// ---------------------------------------------------------------------------
// hi/lo split: src fp32 [4096, 2048] -> dst f16 [4096, 4096] = [hi|lo]
// ---------------------------------------------------------------------------
__global__ __launch_bounds__(256) void cvt_hilo(const float* __restrict__ src,
                                                __half* __restrict__ dst)
{
    int t = blockIdx.x * blockDim.x + threadIdx.x;
    int m  = t >> 9;
    int c4 = (t & 511) * 4;
    float4 x = *(const float4*)(src + (size_t)m * 2048 + c4);

    __half h0 = __float2half_rn(x.x), h1 = __float2half_rn(x.y);
    __half h2 = __float2half_rn(x.z), h3 = __float2half_rn(x.w);
    __half l0 = __float2half_rn(x.x - __half2float(h0));
    __half l1 = __float2half_rn(x.y - __half2float(h1));
    __half l2 = __float2half_rn(x.z - __half2float(h2));
    __half l3 = __float2half_rn(x.w - __half2float(h3));

    __half2 H01 = __halves2half2(h0, h1), H23 = __halves2half2(h2, h3);
    __half2 L01 = __halves2half2(l0, l1), L23 = __halves2half2(l2, l3);
    uint2 Hv = make_uint2(*(uint32_t*)&H01, *(uint32_t*)&H23);
    uint2 Lv = make_uint2(*(uint32_t*)&L01, *(uint32_t*)&L23);

    size_t base = (size_t)m * KA_ + c4;
    *(uint2*)(dst + base)        = Hv;
    *(uint2*)(dst + base + 2048) = Lv;
}

// ---------------------------------------------------------------------------
// Fused weight transpose: all four W at once.
// ---------------------------------------------------------------------------
__global__ __launch_bounds__(256) void cvt_w_all(const float* __restrict__ Wq,
                                                 const float* __restrict__ Wk,
                                                 const float* __restrict__ Wv,
                                                 const float* __restrict__ Wo,
                                                 __half* __restrict__ Pq,
                                                 __half* __restrict__ Pk,
                                                 __half* __restrict__ Pv,
                                                 __half* __restrict__ Po)
{
    __shared__ float tile[32][33];
    int tx = threadIdx.x, ty = threadIdx.y;
    int bxx = blockIdx.x;

    const float* W; __half* Wp; int Nout, nb;
    if (bxx < 64)       { W = Wq; Wp = Pq; Nout = 2048; nb = bxx; }
    else if (bxx < 80)  { W = Wk; Wp = Pk; Nout = 512;  nb = bxx - 64; }
    else if (bxx < 96)  { W = Wv; Wp = Pv; Nout = 512;  nb = bxx - 80; }
    else                { W = Wo; Wp = Po; Nout = 2048; nb = bxx - 96; }

    int n0 = nb * 32, k0 = blockIdx.y * 32;

    #pragma unroll
    for (int r = 0; r < 4; r++)
        tile[ty + r * 8][tx] = W[(size_t)(k0 + ty + r * 8) * Nout + n0 + tx];
    __syncthreads();

    #pragma unroll
    for (int r = 0; r < 4; r++) {
        int nl = ty + r * 8, kl = tx;
        Wp[(size_t)(n0 + nl) * KW_ + k0 + kl] = __float2half_rn(tile[kl][nl]);
    }
}

// ---------------------------------------------------------------------------
// f16 mma.sync GEMM: C = A'[M,4096] @ W'[N,2048,wrapped]^T
// 128x128 CTA tile, 8 warps (2x4), K-slab 64.
// cp.async.cg 3-stage pipeline, ldmatrix fragment loads. (R16-proven)
// ---------------------------------------------------------------------------
#define KSLAB 64
#define NSLAB (KA_ / KSLAB)     // 64
#define ARS   72                // smem row stride in halves (144 B, conflict-free)
#define BUFH  (128 * ARS)       // halves per buffer (9216)
#define GSM_BYTES (6 * BUFH * 2)   // 3 A + 3 B bufs = 110592 B

__device__ __forceinline__ void mma_gemm_body(
    const __half* __restrict__ A2, const __half* __restrict__ W2,
    float* __restrict__ C, int Nout, int row0, int col0)
{
    extern __shared__ __half gsm[];
    __half* Asp = gsm;               // 3 x BUFH
    __half* Bsp = gsm + 3 * BUFH;    // 3 x BUFH

    const int tid  = threadIdx.x;
    const int lane = tid & 31;
    const int wid  = tid >> 5;
    const int wm   = wid >> 2;
    const int wn   = wid & 3;
    const int g    = lane >> 2;
    const int tq   = lane & 3;

    const int lrow = tid >> 2;          // 0..63
    const int lk   = (tid & 3) * 16;    // 0,16,32,48 (halves)

    const __half* Ag = A2 + (size_t)(row0 + lrow) * KA_ + lk;
    const __half* Bg = W2 + (size_t)(col0 + lrow) * KW_ + lk;

    const uint32_t AROW = ARS * 2;      // bytes per smem row (144)
    uint32_t aB[3], bB[3], aD[3], bD[3];
    #pragma unroll
    for (int u = 0; u < 3; u++) {
        aB[u] = smem_u32(Asp + u * BUFH + (wm * 64 + (lane & 15)) * ARS + (lane >> 4) * 8);
        bB[u] = smem_u32(Bsp + u * BUFH + (wn * 32 + (lane >> 4) * 8 + (lane & 7)) * ARS
                         + ((lane >> 3) & 1) * 8);
        aD[u] = smem_u32(Asp + u * BUFH + lrow * ARS + lk);
        bD[u] = smem_u32(Bsp + u * BUFH + lrow * ARS + lk);
    }

    float acc[4][4][4];
    #pragma unroll
    for (int i = 0; i < 4; i++)
        #pragma unroll
        for (int j = 0; j < 4; j++)
            #pragma unroll
            for (int c = 0; c < 4; c++) acc[i][j][c] = 0.f;

    auto issue_slab = [&](int s, int u) {
        const int ka = s * KSLAB;
        const int kw = ka & (KW_ - 1);
        cpa16(aD[u],                      Ag + ka);
        cpa16(aD[u] + 16,                 Ag + ka + 8);
        cpa16(aD[u] + 64 * AROW,          Ag + ka + (size_t)64 * KA_);
        cpa16(aD[u] + 64 * AROW + 16,     Ag + ka + (size_t)64 * KA_ + 8);
        cpa16(bD[u],                      Bg + kw);
        cpa16(bD[u] + 16,                 Bg + kw + 8);
        cpa16(bD[u] + 64 * AROW,          Bg + kw + (size_t)64 * KW_);
        cpa16(bD[u] + 64 * AROW + 16,     Bg + kw + (size_t)64 * KW_ + 8);
    };

    issue_slab(0, 0); CP_COMMIT();
    issue_slab(1, 1); CP_COMMIT();

    int buf = 0;
    for (int s = 0; s < NSLAB; s++) {
        CP_WAIT1();           // slab s resident
        __syncthreads();

        #pragma unroll
        for (int ks = 0; ks < 4; ks++) {
            uint32_t af[4][4];
            #pragma unroll
            for (int mt = 0; mt < 4; mt++)
                ldmx4(af[mt][0], af[mt][1], af[mt][2], af[mt][3],
                      aB[buf] + (uint32_t)(mt * 16) * AROW + ks * 32);
            uint32_t bf[4][2];
            ldmx4(bf[0][0], bf[0][1], bf[1][0], bf[1][1], bB[buf] + ks * 32);
            ldmx4(bf[2][0], bf[2][1], bf[3][0], bf[3][1],
                  bB[buf] + (uint32_t)16 * AROW + ks * 32);

            #pragma unroll
            for (int mt = 0; mt < 4; mt++)
                #pragma unroll
                for (int nt = 0; nt < 4; nt++)
                    mma16816(acc[mt][nt], af[mt], bf[nt]);
        }

        if (s + 2 < NSLAB) issue_slab(s + 2, (s + 2) % 3);
        CP_COMMIT();          // commit every iteration (possibly empty group)
        buf = (buf + 1) % 3;
    }

    #pragma unroll
    for (int mt = 0; mt < 4; mt++) {
        #pragma unroll
        for (int nt = 0; nt < 4; nt++) {
            int row = row0 + wm * 64 + mt * 16 + g;
            int col = col0 + wn * 32 + nt * 8 + tq * 2;
            *(float2*)&C[(size_t)row * Nout + col] =
                make_float2(acc[mt][nt][0], acc[mt][nt][1]);
            *(float2*)&C[(size_t)(row + 8) * Nout + col] =
                make_float2(acc[mt][nt][2], acc[mt][nt][3]);
        }
    }
}

__global__ __launch_bounds__(256, 2) void qkv_mma()
{
    const int bx = blockIdx.x;
    if (bx < 512)
        mma_gemm_body(g_a2, g_wq2, g_q, NH_ * DH_, (bx >> 4) * 128, (bx & 15) * 128);
    else if (bx < 640) {
        int t = bx - 512;
        mma_gemm_body(g_a2, g_wk2, g_k, NKV_ * DH_, (t >> 2) * 128, (t & 3) * 128);
    } else {
        int t = bx - 640;
        mma_gemm_body(g_a2, g_wv2, g_v, NKV_ * DH_, (t >> 2) * 128, (t & 3) * 128);
    }
}

__global__ __launch_bounds__(256, 2) void out_mma(float* __restrict__ out)
{
    const int bx = blockIdx.x;
    mma_gemm_body(g_a2, g_wo2, out, H_, (bx >> 4) * 128, (bx & 15) * 128);
}

// ---------------------------------------------------------------------------
// RoPE + split: g_q -> g_q2 [qh|ql] scaled 1/8 ; g_k -> g_k2 [kh] only
// ---------------------------------------------------------------------------
__global__ __launch_bounds__(256) void rope_split_kernel(const int* __restrict__ pos_ids)
{
    const int TOT = M_ * (NH_ + NKV_) * 32;
    int t = blockIdx.x * blockDim.x + threadIdx.x;
    if (t >= TOT) return;

    int i  = t & 31;
    int h  = (t >> 5) % (NH_ + NKV_);
    int bs = t / (32 * (NH_ + NKV_));
    int b  = bs >> 11, s = bs & 2047;

    float pos = (float)pos_ids[bs];
    float f = pos * g_invfreq[i];
    float sn, c;
    sincosf(f, &sn, &c);

    if (h < NH_) {
        const float* base = g_q + (size_t)bs * (NH_ * DH_) + h * DH_;
        __half* dst = g_q2 + ((size_t)(b * NH_ + h) * S_ + s) * 128;
        float x1 = base[i], x2 = base[i + 32];
        float o1 = (x1 * c - x2 * sn) * 0.125f;
        float o2 = (x2 * c + x1 * sn) * 0.125f;
        __half h1 = __float2half_rn(o1);
        __half h2 = __float2half_rn(o2);
        dst[i]           = h1;
        dst[i + 32]      = h2;
        dst[64 + i]      = __float2half_rn(o1 - __half2float(h1));
        dst[64 + i + 32] = __float2half_rn(o2 - __half2float(h2));
    } else {
        const float* base = g_k + (size_t)bs * (NKV_ * DH_) + (h - NH_) * DH_;
        __half* dst = g_k2 + ((size_t)(b * NKV_ + (h - NH_)) * S_ + s) * 64;
        float x1 = base[i], x2 = base[i + 32];
        dst[i]      = __float2half_rn(x1 * c - x2 * sn);
        dst[i + 32] = __float2half_rn(x2 * c + x1 * sn);
    }
}

// ---------------------------------------------------------------------------
// V transpose: g_v fp32 [m][512] -> g_v2t f16 [b][kvh][d][s] (hi only)
// ---------------------------------------------------------------------------
__global__ __launch_bounds__(256) void cvt_v_kernel()
{
    __shared__ float tile[32][33];
    int tx = threadIdx.x, ty = threadIdx.y;
    int s0 = blockIdx.x * 32;
    int cb = blockIdx.y;
    int b  = blockIdx.z;
    int kvh = cb >> 1, dbase = (cb & 1) * 32;

    #pragma unroll
    for (int r = 0; r < 4; r++)
        tile[ty + r * 8][tx] = g_v[(size_t)(b * S_ + s0 + ty + r * 8) * 512 + cb * 32 + tx];
    __syncthreads();

    #pragma unroll
    for (int r = 0; r < 4; r++) {
        int dl = ty + r * 8;
        size_t obase = ((size_t)(b * NKV_ + kvh) * 64 + dbase + dl) * S_;
        g_v2t[obase + s0 + tx] = __float2half_rn(tile[tx][dl]);
    }
}

// ---------------------------------------------------------------------------
// Flash attention on HMMA. QK uses (Qh+Ql)Kh split; PV uses Ph*Vh only
// (Pl residual dropped: adds ~2.4e-4 RMS, budgeted well under 1e-3).
// ---------------------------------------------------------------------------
#define KSP   72                        // K/Vt smem stride (f16)

__global__ __launch_bounds__(256) void flash_mma()
{
    __shared__ __half Ks[2][64 * KSP];
    __shared__ __half Vt[2][64 * KSP];

    const int tid  = threadIdx.x;
    const int lane = tid & 31;
    const int wq   = tid >> 5;
    const int g    = lane >> 2;
    const int tq   = lane & 3;

    const int jq  = (gridDim.x - 1) - blockIdx.x;
    const int h   = blockIdx.y;
    const int b   = blockIdx.z;
    const int kvh = h >> 2;
    const int q0  = jq * 128;

    const __half* qbase = g_q2 + ((size_t)(b * NH_ + h) * S_ + q0 + wq * 16) * 128;
    const __half* kbase = g_k2 + (size_t)(b * NKV_ + kvh) * S_ * 64;
    const __half* vbase = g_v2t + (size_t)(b * NKV_ + kvh) * 64 * S_;

    const int lr  = tid >> 2;       // 0..63
    const int lsg = tid & 3;        // 16-half segment

    const uint32_t KROW = KSP * 2;
    uint32_t kB[2], vB[2], kD[2], vD[2];
    #pragma unroll
    for (int u = 0; u < 2; u++) {
        kB[u] = smem_u32(&Ks[u][((lane >> 4) * 8 + (lane & 7)) * KSP + ((lane >> 3) & 1) * 8]);
        vB[u] = smem_u32(&Vt[u][((lane >> 4) * 8 + (lane & 7)) * KSP + ((lane >> 3) & 1) * 8]);
        kD[u] = smem_u32(&Ks[u][lr * KSP + lsg * 16]);
        vD[u] = smem_u32(&Vt[u][lr * KSP + lsg * 16]);
    }

    auto issue_kv = [&](int jt, int u) {
        const __half* ks = kbase + (size_t)(jt * 64 + lr) * 64 + lsg * 16;
        const __half* vs = vbase + (size_t)lr * S_ + jt * 64 + lsg * 16;
        cpa16(kD[u],      ks);
        cpa16(kD[u] + 16, ks + 8);
        cpa16(vD[u],      vs);
        cpa16(vD[u] + 16, vs + 8);
    };

    uint32_t qf[8][4];
    #pragma unroll
    for (int pc = 0; pc < 8; pc++) {
        int c = pc * 16 + tq * 2;
        qf[pc][0] = *(const uint32_t*)(qbase + (size_t)g * 128 + c);
        qf[pc][1] = *(const uint32_t*)(qbase + (size_t)(g + 8) * 128 + c);
        qf[pc][2] = *(const uint32_t*)(qbase + (size_t)g * 128 + c + 8);
        qf[pc][3] = *(const uint32_t*)(qbase + (size_t)(g + 8) * 128 + c + 8);
    }

    float m0 = -1e30f, m1 = -1e30f, l0 = 0.f, l1 = 0.f;
    float accO[8][4];
    #pragma unroll
    for (int nt = 0; nt < 8; nt++)
        #pragma unroll
        for (int c = 0; c < 4; c++) accO[nt][c] = 0.f;

    issue_kv(0, 0); CP_COMMIT();
    CP_WAIT0();
    __syncthreads();

    int fb = 0;
    const int ntiles = 2 * jq + 2;
    for (int jt = 0; jt < ntiles; jt++) {
        const bool more = (jt + 1 < ntiles);
        if (more) { issue_kv(jt + 1, fb ^ 1); CP_COMMIT(); }

        float sa[8][4];
        #pragma unroll
        for (int nt = 0; nt < 8; nt++)
            #pragma unroll
            for (int c = 0; c < 4; c++) sa[nt][c] = 0.f;

        #pragma unroll
        for (int kc = 0; kc < 4; kc++) {
            uint32_t bf[8][2];
            #pragma unroll
            for (int ntp = 0; ntp < 4; ntp++)
                ldmx4(bf[2*ntp][0], bf[2*ntp][1], bf[2*ntp+1][0], bf[2*ntp+1][1],
                      kB[fb] + (uint32_t)(ntp * 16) * KROW + kc * 32);
            #pragma unroll
            for (int nt = 0; nt < 8; nt++) {
                mma16816(sa[nt], qf[kc],     bf[nt]);
                mma16816(sa[nt], qf[kc + 4], bf[nt]);
            }
        }

        const float NEG = -1e30f;
        if (jt >= 2 * jq) {
            int rg0 = q0 + wq * 16 + g, rg1 = rg0 + 8;
            #pragma unroll
            for (int nt = 0; nt < 8; nt++) {
                int cg = jt * 64 + nt * 8 + tq * 2;
                if (cg     > rg0) sa[nt][0] = NEG;
                if (cg + 1 > rg0) sa[nt][1] = NEG;
                if (cg     > rg1) sa[nt][2] = NEG;
                if (cg + 1 > rg1) sa[nt][3] = NEG;
            }
        }

        float rm0 = NEG, rm1 = NEG;
        #pragma unroll
        for (int nt = 0; nt < 8; nt++) {
            rm0 = fmaxf(rm0, fmaxf(sa[nt][0], sa[nt][1]));
            rm1 = fmaxf(rm1, fmaxf(sa[nt][2], sa[nt][3]));
        }
        rm0 = fmaxf(rm0, __shfl_xor_sync(0xffffffffu, rm0, 1));
        rm0 = fmaxf(rm0, __shfl_xor_sync(0xffffffffu, rm0, 2));
        rm1 = fmaxf(rm1, __shfl_xor_sync(0xffffffffu, rm1, 1));
        rm1 = fmaxf(rm1, __shfl_xor_sync(0xffffffffu, rm1, 2));

        float mn0 = fmaxf(m0, rm0), mn1 = fmaxf(m1, rm1);
        float al0 = __expf(m0 - mn0), al1 = __expf(m1 - mn1);
        m0 = mn0; m1 = mn1;

        float rs0 = 0.f, rs1 = 0.f;
        float p[8][4];
        #pragma unroll
        for (int nt = 0; nt < 8; nt++) {
            p[nt][0] = __expf(sa[nt][0] - mn0);
            p[nt][1] = __expf(sa[nt][1] - mn0);
            p[nt][2] = __expf(sa[nt][2] - mn1);
            p[nt][3] = __expf(sa[nt][3] - mn1);
            rs0 += p[nt][0] + p[nt][1];
            rs1 += p[nt][2] + p[nt][3];
        }
        rs0 += __shfl_xor_sync(0xffffffffu, rs0, 1);
        rs0 += __shfl_xor_sync(0xffffffffu, rs0, 2);
        rs1 += __shfl_xor_sync(0xffffffffu, rs1, 1);
        rs1 += __shfl_xor_sync(0xffffffffu, rs1, 2);
        l0 = l0 * al0 + rs0;
        l1 = l1 * al1 + rs1;

        #pragma unroll
        for (int nt = 0; nt < 8; nt++) {
            accO[nt][0] *= al0; accO[nt][1] *= al0;
            accO[nt][2] *= al1; accO[nt][3] *= al1;
        }

        // ---- O += Ph Vh (Pl residual dropped) ----
        #pragma unroll
        for (int vc = 0; vc < 4; vc++) {
            uint32_t aph[4];
            aph[0] = packh(p[2*vc][0],   p[2*vc][1]);
            aph[1] = packh(p[2*vc][2],   p[2*vc][3]);
            aph[2] = packh(p[2*vc+1][0], p[2*vc+1][1]);
            aph[3] = packh(p[2*vc+1][2], p[2*vc+1][3]);

            uint32_t bf[8][2];
            #pragma unroll
            for (int ntp = 0; ntp < 4; ntp++)
                ldmx4(bf[2*ntp][0], bf[2*ntp][1], bf[2*ntp+1][0], bf[2*ntp+1][1],
                      vB[fb] + (uint32_t)(ntp * 16) * KROW + vc * 32);
            #pragma unroll
            for (int nt = 0; nt < 8; nt++)
                mma16816(accO[nt], aph, bf[nt]);
        }

        if (more) {
            CP_WAIT0();
            __syncthreads();
            fb ^= 1;
        }
    }

    float inv0 = 1.f / l0, inv1 = 1.f / l1;
    size_t r0 = (size_t)b * S_ + q0 + wq * 16 + g;
    #pragma unroll
    for (int nt = 0; nt < 8; nt++) {
        int c = h * 64 + nt * 8 + tq * 2;
        float o00 = accO[nt][0] * inv0, o01 = accO[nt][1] * inv0;
        float o10 = accO[nt][2] * inv1, o11 = accO[nt][3] * inv1;

        __half h00 = __float2half_rn(o00), h01 = __float2half_rn(o01);
        __half h10 = __float2half_rn(o10), h11 = __float2half_rn(o11);

        __half* d0 = g_a2 + r0 * KA_ + c;
        __half* d1 = g_a2 + (r0 + 8) * KA_ + c;
        *(uint32_t*)(d0)        = packh(o00, o01);
        *(uint32_t*)(d0 + 2048) = packh(o00 - __half2float(h00), o01 - __half2float(h01));
        *(uint32_t*)(d1)        = packh(o10, o11);
        *(uint32_t*)(d1 + 2048) = packh(o10 - __half2float(h10), o11 - __half2float(h11));
    }
}

// ---------------------------------------------------------------------------
// launch
// ---------------------------------------------------------------------------
extern "C" void kernel_launch(void* const* d_in, const int* in_sizes, int n_in,
                              void* d_out, int out_size)
{
    const float* X   = (const float*)d_in[0];
    const int*   pos = (const int*)  d_in[1];
    const float* Wq  = (const float*)d_in[2];
    const float* Wk  = (const float*)d_in[3];
    const float* Wv  = (const float*)d_in[4];
    const float* Wo  = (const float*)d_in[5];
    float*       out = (float*)d_out;

    void *pa2, *pwq, *pwk, *pwv, *pwo;
    cudaGetSymbolAddress(&pa2, g_a2);
    cudaGetSymbolAddress(&pwq, g_wq2);
    cudaGetSymbolAddress(&pwk, g_wk2);
    cudaGetSymbolAddress(&pwv, g_wv2);
    cudaGetSymbolAddress(&pwo, g_wo2);

    cudaFuncSetAttribute(qkv_mma, cudaFuncAttributeMaxDynamicSharedMemorySize, GSM_BYTES);
    cudaFuncSetAttribute(out_mma, cudaFuncAttributeMaxDynamicSharedMemorySize, GSM_BYTES);

    invfreq_init_kernel<<<1, 32>>>();

    cvt_hilo<<<8192, 256>>>(X, (__half*)pa2);
    cvt_w_all<<<dim3(160, 64), dim3(32, 8)>>>(Wq, Wk, Wv, Wo,
        (__half*)pwq, (__half*)pwk, (__half*)pwv, (__half*)pwo);

    qkv_mma<<<768, 256, GSM_BYTES>>>();

    {
        const int TOT = M_ * (NH_ + NKV_) * 32;
        rope_split_kernel<<<(TOT + 255) / 256, 256>>>(pos);
    }
    cvt_v_kernel<<<dim3(64, 16, 2), dim3(32, 8)>>>();

    flash_mma<<<dim3(S_ / 128, NH_, B_), 256>>>();

    out_mma<<<512, 256, GSM_BYTES>>>(out);
}